// round 2
// baseline (speedup 1.0000x reference)
#include <cuda_runtime.h>
#include <cuda_bf16.h>
#include <stdint.h>

#define TOKENS   65536
#define KD       512
#define NC1      1536
#define NHEADS   16
#define SCALE_Q  0.17677669529663688f

// ------------------------- device scratch (static) -------------------------
__device__ __nv_bfloat16 g_q_hi  [TOKENS * KD];
__device__ __nv_bfloat16 g_q_lo  [TOKENS * KD];
__device__ __nv_bfloat16 g_w1_hi [KD * NC1];
__device__ __nv_bfloat16 g_w1_lo [KD * NC1];
__device__ __nv_bfloat16 g_w3_hi [KD * KD];
__device__ __nv_bfloat16 g_w3_lo [KD * KD];
__device__ __nv_bfloat16 g_qkv_hi[(size_t)TOKENS * NC1];
__device__ __nv_bfloat16 g_qkv_lo[(size_t)TOKENS * NC1];
__device__ __nv_bfloat16 g_o_hi  [TOKENS * KD];
__device__ __nv_bfloat16 g_o_lo  [TOKENS * KD];

// ------------------------------ PTX helpers --------------------------------
__device__ __forceinline__ uint32_t smem_u32(const void* p) {
    return (uint32_t)__cvta_generic_to_shared(p);
}
__device__ __forceinline__ void cp16(void* s, const void* g) {
    asm volatile("cp.async.cg.shared.global [%0], [%1], 16;\n"
                 :: "r"(smem_u32(s)), "l"(g));
}
__device__ __forceinline__ void cp_commit() { asm volatile("cp.async.commit_group;\n"); }
template<int N> __device__ __forceinline__ void cp_wait() {
    asm volatile("cp.async.wait_group %0;\n" :: "n"(N));
}
__device__ __forceinline__ void ldsm4(uint32_t r[4], const void* p) {
    asm volatile("ldmatrix.sync.aligned.m8n8.x4.shared.b16 {%0,%1,%2,%3}, [%4];\n"
        : "=r"(r[0]), "=r"(r[1]), "=r"(r[2]), "=r"(r[3]) : "r"(smem_u32(p)));
}
__device__ __forceinline__ void ldsm4t(uint32_t r[4], const void* p) {
    asm volatile("ldmatrix.sync.aligned.m8n8.x4.trans.shared.b16 {%0,%1,%2,%3}, [%4];\n"
        : "=r"(r[0]), "=r"(r[1]), "=r"(r[2]), "=r"(r[3]) : "r"(smem_u32(p)));
}
__device__ __forceinline__ void mma_bf16(float c[4], const uint32_t a[4], const uint32_t b[2]) {
    asm volatile(
        "mma.sync.aligned.m16n8k16.row.col.f32.bf16.bf16.f32 "
        "{%0,%1,%2,%3}, {%4,%5,%6,%7}, {%8,%9}, {%0,%1,%2,%3};\n"
        : "+f"(c[0]), "+f"(c[1]), "+f"(c[2]), "+f"(c[3])
        : "r"(a[0]), "r"(a[1]), "r"(a[2]), "r"(a[3]), "r"(b[0]), "r"(b[1]));
}
__device__ __forceinline__ void store_split2(__nv_bfloat16* ph, __nv_bfloat16* pl,
                                             float v0, float v1) {
    __nv_bfloat16 h0 = __float2bfloat16(v0);
    __nv_bfloat16 h1 = __float2bfloat16(v1);
    __nv_bfloat16 l0 = __float2bfloat16(v0 - __bfloat162float(h0));
    __nv_bfloat16 l1 = __float2bfloat16(v1 - __bfloat162float(h1));
    *reinterpret_cast<__nv_bfloat162*>(ph) = __halves2bfloat162(h0, h1);
    *reinterpret_cast<__nv_bfloat162*>(pl) = __halves2bfloat162(l0, l1);
}

// ------------------------------ prep kernels -------------------------------
__global__ void split_f32_kernel(const float* __restrict__ src,
                                 __nv_bfloat16* __restrict__ hi,
                                 __nv_bfloat16* __restrict__ lo, int n) {
    int i = blockIdx.x * blockDim.x + threadIdx.x;
    if (i >= n) return;
    float v = src[i];
    __nv_bfloat16 h = __float2bfloat16(v);
    hi[i] = h;
    lo[i] = __float2bfloat16(v - __bfloat162float(h));
}

__global__ void split_w1_kernel(const float* __restrict__ wq,
                                const float* __restrict__ wkv) {
    int i = blockIdx.x * blockDim.x + threadIdx.x;
    if (i >= KD * NC1) return;
    int k = i / NC1, n = i - k * NC1;
    float v = (n < KD) ? wq[k * KD + n] : wkv[k * 1024 + (n - KD)];
    __nv_bfloat16 h = __float2bfloat16(v);
    g_w1_hi[i] = h;
    g_w1_lo[i] = __float2bfloat16(v - __bfloat162float(h));
}

// --------------------- split-bf16 GEMM, 128x128x32 tiles -------------------
// MODE 1: QKV epilogue (bias + Q scale, split-bf16 out). MODE 3: fp32 out.
template<int NCOLS, int MODE>
__global__ __launch_bounds__(256, 2)
void gemm_kernel(const __nv_bfloat16* __restrict__ Ah, const __nv_bfloat16* __restrict__ Al,
                 const __nv_bfloat16* __restrict__ Bh, const __nv_bfloat16* __restrict__ Bl,
                 const float* __restrict__ bias0, const float* __restrict__ bias1,
                 __nv_bfloat16* __restrict__ outh, __nv_bfloat16* __restrict__ outl,
                 float* __restrict__ outf)
{
    constexpr int SA = 40;
    constexpr int SB = 136;
    constexpr int NB = NCOLS / 128;
    constexpr int GROUP_M = 16;
    extern __shared__ char smem_raw[];
    __nv_bfloat16* sA = (__nv_bfloat16*)smem_raw;   // [2][hi/lo][128*SA]
    __nv_bfloat16* sB = sA + 2 * 2 * 128 * SA;      // [2][hi/lo][ 32*SB]

    int bid = blockIdx.x;
    int gsz = GROUP_M * NB;
    int grp = bid / gsz;
    int rem = bid - grp * gsz;
    int bm  = grp * GROUP_M + (rem % GROUP_M);
    int bn  = rem / GROUP_M;

    int tid = threadIdx.x, lane = tid & 31, wid = tid >> 5;
    int wm = wid & 3, wn = wid >> 2;
    const int arow = tid >> 2, acol8 = (tid & 3) * 8;
    const int brow = tid >> 4, bcol8 = (tid & 15) * 8;

    auto load_stage = [&](int st, int k0) {
        __nv_bfloat16* dAh = sA + st * (2 * 128 * SA);
        __nv_bfloat16* dAl = dAh + 128 * SA;
        __nv_bfloat16* dBh = sB + st * (2 * 32 * SB);
        __nv_bfloat16* dBl = dBh + 32 * SB;
        size_t ga = (size_t)(bm * 128 + arow) * KD + k0 + acol8;
        cp16(dAh + arow * SA + acol8,        Ah + ga);
        cp16(dAh + (arow + 64) * SA + acol8, Ah + ga + (size_t)64 * KD);
        cp16(dAl + arow * SA + acol8,        Al + ga);
        cp16(dAl + (arow + 64) * SA + acol8, Al + ga + (size_t)64 * KD);
        size_t gb = (size_t)(k0 + brow) * NCOLS + bn * 128 + bcol8;
        cp16(dBh + brow * SB + bcol8,        Bh + gb);
        cp16(dBh + (brow + 16) * SB + bcol8, Bh + gb + (size_t)16 * NCOLS);
        cp16(dBl + brow * SB + bcol8,        Bl + gb);
        cp16(dBl + (brow + 16) * SB + bcol8, Bl + gb + (size_t)16 * NCOLS);
    };

    float acc[2][8][4];
    #pragma unroll
    for (int a = 0; a < 2; a++)
        #pragma unroll
        for (int b = 0; b < 8; b++)
            #pragma unroll
            for (int c = 0; c < 4; c++) acc[a][b][c] = 0.f;

    load_stage(0, 0);
    cp_commit();

    for (int kt = 0; kt < KD / 32; kt++) {
        if (kt + 1 < KD / 32) {
            load_stage((kt + 1) & 1, (kt + 1) * 32);
            cp_commit();
            cp_wait<1>();
        } else {
            cp_wait<0>();
        }
        __syncthreads();

        const __nv_bfloat16* cAh = sA + (kt & 1) * (2 * 128 * SA);
        const __nv_bfloat16* cAl = cAh + 128 * SA;
        const __nv_bfloat16* cBh = sB + (kt & 1) * (2 * 32 * SB);
        const __nv_bfloat16* cBl = cBh + 32 * SB;

        #pragma unroll
        for (int kk = 0; kk < 2; kk++) {
            uint32_t ah0[4], ah1[4], al0[4], al1[4];
            int ar = wm * 32 + (lane & 15);
            int ac = kk * 16 + (lane >> 4) * 8;
            ldsm4(ah0, cAh + ar * SA + ac);
            ldsm4(ah1, cAh + (ar + 16) * SA + ac);
            ldsm4(al0, cAl + ar * SA + ac);
            ldsm4(al1, cAl + (ar + 16) * SA + ac);
            int br = kk * 16 + (lane & 15);
            #pragma unroll
            for (int nj2 = 0; nj2 < 4; nj2++) {
                int bc = wn * 64 + nj2 * 16 + (lane >> 4) * 8;
                uint32_t bh[4], bl[4];
                ldsm4t(bh, cBh + br * SB + bc);
                ldsm4t(bl, cBl + br * SB + bc);
                #pragma unroll
                for (int t = 0; t < 2; t++) {
                    int nj = nj2 * 2 + t;
                    mma_bf16(acc[0][nj], ah0, bh + 2 * t);
                    mma_bf16(acc[0][nj], ah0, bl + 2 * t);
                    mma_bf16(acc[0][nj], al0, bh + 2 * t);
                    mma_bf16(acc[1][nj], ah1, bh + 2 * t);
                    mma_bf16(acc[1][nj], ah1, bl + 2 * t);
                    mma_bf16(acc[1][nj], al1, bh + 2 * t);
                }
            }
        }
        __syncthreads();
    }

    int row0 = bm * 128 + wm * 32 + (lane >> 2);
    int col0 = bn * 128 + wn * 64 + (lane & 3) * 2;
    #pragma unroll
    for (int mi = 0; mi < 2; mi++) {
        int ra = row0 + mi * 16;
        #pragma unroll
        for (int nj = 0; nj < 8; nj++) {
            int col = col0 + nj * 8;
            if (MODE == 1) {
                float b0, b1; float sc0, sc1;
                if (col < 512) { b0 = bias0[col]; b1 = bias0[col + 1]; sc0 = SCALE_Q; sc1 = SCALE_Q; }
                else { b0 = bias1[col - 512]; b1 = bias1[col - 511]; sc0 = 1.f; sc1 = 1.f; }
                size_t g0 = (size_t)ra * NCOLS + col;
                store_split2(outh + g0, outl + g0,
                             (acc[mi][nj][0] + b0) * sc0, (acc[mi][nj][1] + b1) * sc1);
                size_t g1 = (size_t)(ra + 8) * NCOLS + col;
                store_split2(outh + g1, outl + g1,
                             (acc[mi][nj][2] + b0) * sc0, (acc[mi][nj][3] + b1) * sc1);
            } else {
                float b0 = bias0[col], b1 = bias0[col + 1];
                float2 v01 = make_float2(acc[mi][nj][0] + b0, acc[mi][nj][1] + b1);
                float2 v23 = make_float2(acc[mi][nj][2] + b0, acc[mi][nj][3] + b1);
                *(float2*)&outf[(size_t)ra * NCOLS + col]       = v01;
                *(float2*)&outf[(size_t)(ra + 8) * NCOLS + col] = v23;
            }
        }
    }
}

// ----------------------------- attention kernel ----------------------------
// 1 CTA (128 thr) per (window, head). Exact fp32 softmax; attn is an output.
__global__ __launch_bounds__(128)
void attn_kernel(const __nv_bfloat16* __restrict__ qkvh,
                 const __nv_bfloat16* __restrict__ qkvl,
                 const float* __restrict__ table,
                 const int* __restrict__ relidx,
                 float* __restrict__ attn_out,
                 __nv_bfloat16* __restrict__ oh, __nv_bfloat16* __restrict__ ol)
{
    extern __shared__ float sm[];
    float* sQ = sm;                 // 64*36
    float* sK = sQ + 64 * 36;
    float* sV = sK + 64 * 36;
    float* sP = sV + 64 * 36;       // 64*66
    float* sTab = sP + 64 * 66;     // 228
    uint8_t* sIdx = (uint8_t*)(sTab + 228);  // 4096

    int w = blockIdx.x >> 4, h = blockIdx.x & 15;
    int tid = threadIdx.x, lane = tid & 31, wr = tid >> 5;
    const size_t base = (size_t)(w * 64) * NC1 + h * 32;

    for (int e = tid; e < 2048; e += 128) {
        int i = e >> 5, d = e & 31;
        size_t g = base + (size_t)i * NC1 + d;
        sQ[i * 36 + d] = __bfloat162float(qkvh[g])        + __bfloat162float(qkvl[g]);
        sK[i * 36 + d] = __bfloat162float(qkvh[g + 512])  + __bfloat162float(qkvl[g + 512]);
        sV[i * 36 + d] = __bfloat162float(qkvh[g + 1024]) + __bfloat162float(qkvl[g + 1024]);
    }
    for (int t = tid; t < 4096; t += 128) sIdx[t] = (uint8_t)relidx[t];
    for (int t = tid; t < 225; t += 128)  sTab[t] = table[t * NHEADS + h];
    __syncthreads();

    // ---- S = Q K^T : warp wr owns rows [wr*16, wr*16+16), lane owns cols lane, lane+32
    int r0 = wr * 16;
    float acc0[16], acc1[16];
    #pragma unroll
    for (int i = 0; i < 16; i++) { acc0[i] = 0.f; acc1[i] = 0.f; }

    #pragma unroll
    for (int dc = 0; dc < 2; dc++) {
        float k0[16], k1[16];
        #pragma unroll
        for (int d4 = 0; d4 < 4; d4++) {
            float4 a = *(const float4*)&sK[lane * 36 + dc * 16 + d4 * 4];
            k0[d4*4] = a.x; k0[d4*4+1] = a.y; k0[d4*4+2] = a.z; k0[d4*4+3] = a.w;
            float4 b = *(const float4*)&sK[(lane + 32) * 36 + dc * 16 + d4 * 4];
            k1[d4*4] = b.x; k1[d4*4+1] = b.y; k1[d4*4+2] = b.z; k1[d4*4+3] = b.w;
        }
        #pragma unroll
        for (int i = 0; i < 16; i++) {
            #pragma unroll
            for (int d4 = 0; d4 < 4; d4++) {
                float4 q = *(const float4*)&sQ[(r0 + i) * 36 + dc * 16 + d4 * 4];
                acc0[i] = fmaf(q.x, k0[d4*4],   acc0[i]);
                acc0[i] = fmaf(q.y, k0[d4*4+1], acc0[i]);
                acc0[i] = fmaf(q.z, k0[d4*4+2], acc0[i]);
                acc0[i] = fmaf(q.w, k0[d4*4+3], acc0[i]);
                acc1[i] = fmaf(q.x, k1[d4*4],   acc1[i]);
                acc1[i] = fmaf(q.y, k1[d4*4+1], acc1[i]);
                acc1[i] = fmaf(q.z, k1[d4*4+2], acc1[i]);
                acc1[i] = fmaf(q.w, k1[d4*4+3], acc1[i]);
            }
        }
    }

    // ---- bias + softmax per row, write attn + stash P ----
    #pragma unroll
    for (int i = 0; i < 16; i++) {
        int row = r0 + i;
        float s0 = acc0[i] + sTab[sIdx[row * 64 + lane]];
        float s1 = acc1[i] + sTab[sIdx[row * 64 + lane + 32]];
        float m = fmaxf(s0, s1);
        #pragma unroll
        for (int o = 16; o > 0; o >>= 1) m = fmaxf(m, __shfl_xor_sync(0xffffffffu, m, o));
        float e0 = __expf(s0 - m), e1 = __expf(s1 - m);
        float sum = e0 + e1;
        #pragma unroll
        for (int o = 16; o > 0; o >>= 1) sum += __shfl_xor_sync(0xffffffffu, sum, o);
        float inv = 1.f / sum;
        float p0 = e0 * inv, p1 = e1 * inv;
        size_t ga = ((size_t)blockIdx.x * 64 + row) * 64 + lane;
        attn_out[ga] = p0;
        attn_out[ga + 32] = p1;
        sP[row * 66 + lane] = p0;
        sP[row * 66 + lane + 32] = p1;
    }
    __syncthreads();

    // ---- O = P V : thread owns (row = tid>>1, 16 dims) ----
    int orow = tid >> 1, dbase = (tid & 1) * 16;
    float o[16];
    #pragma unroll
    for (int d = 0; d < 16; d++) o[d] = 0.f;
    #pragma unroll 8
    for (int j = 0; j < 64; j++) {
        float p = sP[orow * 66 + j];
        #pragma unroll
        for (int d4 = 0; d4 < 4; d4++) {
            float4 v = *(const float4*)&sV[j * 36 + dbase + d4 * 4];
            o[d4*4]   = fmaf(p, v.x, o[d4*4]);
            o[d4*4+1] = fmaf(p, v.y, o[d4*4+1]);
            o[d4*4+2] = fmaf(p, v.z, o[d4*4+2]);
            o[d4*4+3] = fmaf(p, v.w, o[d4*4+3]);
        }
    }
    size_t gb = (size_t)(w * 64 + orow) * KD + h * 32 + dbase;
    #pragma unroll
    for (int d2 = 0; d2 < 8; d2++)
        store_split2(oh + gb + d2 * 2, ol + gb + d2 * 2, o[d2 * 2], o[d2 * 2 + 1]);
}

// ------------------------------- launcher ----------------------------------
extern "C" void kernel_launch(void* const* d_in, const int* in_sizes, int n_in,
                              void* d_out, int out_size) {
    const float* q      = (const float*)d_in[0];
    const float* wq     = (const float*)d_in[1];
    const float* bq     = (const float*)d_in[2];
    const float* wkv    = (const float*)d_in[3];
    const float* bkv    = (const float*)d_in[4];
    const float* wproj  = (const float*)d_in[5];
    const float* bproj  = (const float*)d_in[6];
    const float* table  = (const float*)d_in[7];
    const int*   relidx = (const int*)d_in[8];

    float* out_x    = (float*)d_out;
    float* out_attn = out_x + (size_t)TOKENS * KD;   // x [65536*512] then attn

    __nv_bfloat16 *q_hi, *q_lo, *w1_hi, *w1_lo, *w3_hi, *w3_lo;
    __nv_bfloat16 *qkv_hi, *qkv_lo, *o_hi, *o_lo;
    cudaGetSymbolAddress((void**)&q_hi,   g_q_hi);
    cudaGetSymbolAddress((void**)&q_lo,   g_q_lo);
    cudaGetSymbolAddress((void**)&w1_hi,  g_w1_hi);
    cudaGetSymbolAddress((void**)&w1_lo,  g_w1_lo);
    cudaGetSymbolAddress((void**)&w3_hi,  g_w3_hi);
    cudaGetSymbolAddress((void**)&w3_lo,  g_w3_lo);
    cudaGetSymbolAddress((void**)&qkv_hi, g_qkv_hi);
    cudaGetSymbolAddress((void**)&qkv_lo, g_qkv_lo);
    cudaGetSymbolAddress((void**)&o_hi,   g_o_hi);
    cudaGetSymbolAddress((void**)&o_lo,   g_o_lo);

    const int smem_gemm = (2 * 2 * 128 * 40 + 2 * 2 * 32 * 136) * 2;    // 75776
    const int smem_attn = (3 * 64 * 36 + 64 * 66 + 228) * 4 + 4096;     // 49552
    cudaFuncSetAttribute(gemm_kernel<NC1, 1>, cudaFuncAttributeMaxDynamicSharedMemorySize, smem_gemm);
    cudaFuncSetAttribute(gemm_kernel<KD, 3>,  cudaFuncAttributeMaxDynamicSharedMemorySize, smem_gemm);
    cudaFuncSetAttribute(attn_kernel, cudaFuncAttributeMaxDynamicSharedMemorySize, smem_attn);

    // 1) split inputs
    split_f32_kernel<<<(TOKENS * KD) / 256, 256>>>(q, q_hi, q_lo, TOKENS * KD);
    split_w1_kernel<<<(KD * NC1) / 256, 256>>>(wq, wkv);
    split_f32_kernel<<<(KD * KD) / 256, 256>>>(wproj, w3_hi, w3_lo, KD * KD);

    // 2) QKV projection
    gemm_kernel<NC1, 1><<<(TOKENS / 128) * (NC1 / 128), 256, smem_gemm>>>(
        q_hi, q_lo, w1_hi, w1_lo, bq, bkv, qkv_hi, qkv_lo, nullptr);

    // 3) attention (softmax output + O scratch)
    attn_kernel<<<1024 * NHEADS, 128, smem_attn>>>(
        qkv_hi, qkv_lo, table, relidx, out_attn, o_hi, o_lo);

    // 4) output projection
    gemm_kernel<KD, 3><<<(TOKENS / 128) * (KD / 128), 256, smem_gemm>>>(
        o_hi, o_lo, w3_hi, w3_lo, bproj, nullptr, nullptr, nullptr, out_x);
}

// round 3
// speedup vs baseline: 1.3079x; 1.3079x over previous
#include <cuda_runtime.h>
#include <cuda_bf16.h>
#include <stdint.h>

#define TOKENS   65536
#define KD       512
#define NC1      1536
#define NHEADS   16
#define SCALE_Q  0.17677669529663688f

// ------------------------- device scratch (static) -------------------------
__device__ __nv_bfloat16 g_q_hi  [TOKENS * KD];
__device__ __nv_bfloat16 g_q_lo  [TOKENS * KD];
__device__ __nv_bfloat16 g_w1_hi [KD * NC1];
__device__ __nv_bfloat16 g_w1_lo [KD * NC1];
__device__ __nv_bfloat16 g_w3_hi [KD * KD];
__device__ __nv_bfloat16 g_w3_lo [KD * KD];
__device__ __nv_bfloat16 g_qkv_hi[(size_t)TOKENS * NC1];
__device__ __nv_bfloat16 g_qkv_lo[(size_t)TOKENS * NC1];
__device__ __nv_bfloat16 g_o_hi  [TOKENS * KD];
__device__ __nv_bfloat16 g_o_lo  [TOKENS * KD];

// ------------------------------ PTX helpers --------------------------------
__device__ __forceinline__ uint32_t smem_u32(const void* p) {
    return (uint32_t)__cvta_generic_to_shared(p);
}
__device__ __forceinline__ void cp16(void* s, const void* g) {
    asm volatile("cp.async.cg.shared.global [%0], [%1], 16;\n"
                 :: "r"(smem_u32(s)), "l"(g));
}
__device__ __forceinline__ void cp_commit() { asm volatile("cp.async.commit_group;\n"); }
template<int N> __device__ __forceinline__ void cp_wait() {
    asm volatile("cp.async.wait_group %0;\n" :: "n"(N));
}
__device__ __forceinline__ void ldsm4(uint32_t r[4], const void* p) {
    asm volatile("ldmatrix.sync.aligned.m8n8.x4.shared.b16 {%0,%1,%2,%3}, [%4];\n"
        : "=r"(r[0]), "=r"(r[1]), "=r"(r[2]), "=r"(r[3]) : "r"(smem_u32(p)));
}
__device__ __forceinline__ void ldsm4t(uint32_t r[4], const void* p) {
    asm volatile("ldmatrix.sync.aligned.m8n8.x4.trans.shared.b16 {%0,%1,%2,%3}, [%4];\n"
        : "=r"(r[0]), "=r"(r[1]), "=r"(r[2]), "=r"(r[3]) : "r"(smem_u32(p)));
}
__device__ __forceinline__ void mma_bf16(float c[4], const uint32_t a[4], const uint32_t b[2]) {
    asm volatile(
        "mma.sync.aligned.m16n8k16.row.col.f32.bf16.bf16.f32 "
        "{%0,%1,%2,%3}, {%4,%5,%6,%7}, {%8,%9}, {%0,%1,%2,%3};\n"
        : "+f"(c[0]), "+f"(c[1]), "+f"(c[2]), "+f"(c[3])
        : "r"(a[0]), "r"(a[1]), "r"(a[2]), "r"(a[3]), "r"(b[0]), "r"(b[1]));
}
__device__ __forceinline__ void store_split2(__nv_bfloat16* ph, __nv_bfloat16* pl,
                                             float v0, float v1) {
    __nv_bfloat16 h0 = __float2bfloat16(v0);
    __nv_bfloat16 h1 = __float2bfloat16(v1);
    __nv_bfloat16 l0 = __float2bfloat16(v0 - __bfloat162float(h0));
    __nv_bfloat16 l1 = __float2bfloat16(v1 - __bfloat162float(h1));
    *reinterpret_cast<__nv_bfloat162*>(ph) = __halves2bfloat162(h0, h1);
    *reinterpret_cast<__nv_bfloat162*>(pl) = __halves2bfloat162(l0, l1);
}
__device__ __forceinline__ void pack_split(float a, float b, uint32_t& hi, uint32_t& lo) {
    __nv_bfloat16 ah = __float2bfloat16(a);
    __nv_bfloat16 bh = __float2bfloat16(b);
    __nv_bfloat162 h2 = __halves2bfloat162(ah, bh);
    __nv_bfloat162 l2 = __halves2bfloat162(
        __float2bfloat16(a - __bfloat162float(ah)),
        __float2bfloat16(b - __bfloat162float(bh)));
    hi = *reinterpret_cast<uint32_t*>(&h2);
    lo = *reinterpret_cast<uint32_t*>(&l2);
}

// ------------------------------ prep kernels -------------------------------
__global__ void split_f32_kernel(const float* __restrict__ src,
                                 __nv_bfloat16* __restrict__ hi,
                                 __nv_bfloat16* __restrict__ lo, int n) {
    int i = blockIdx.x * blockDim.x + threadIdx.x;
    if (i >= n) return;
    float v = src[i];
    __nv_bfloat16 h = __float2bfloat16(v);
    hi[i] = h;
    lo[i] = __float2bfloat16(v - __bfloat162float(h));
}

__global__ void split_w1_kernel(const float* __restrict__ wq,
                                const float* __restrict__ wkv) {
    int i = blockIdx.x * blockDim.x + threadIdx.x;
    if (i >= KD * NC1) return;
    int k = i / NC1, n = i - k * NC1;
    float v = (n < KD) ? wq[k * KD + n] : wkv[k * 1024 + (n - KD)];
    __nv_bfloat16 h = __float2bfloat16(v);
    g_w1_hi[i] = h;
    g_w1_lo[i] = __float2bfloat16(v - __bfloat162float(h));
}

// --------------------- split-bf16 GEMM, 128x128x32 tiles -------------------
template<int NCOLS, int MODE>
__global__ __launch_bounds__(256, 2)
void gemm_kernel(const __nv_bfloat16* __restrict__ Ah, const __nv_bfloat16* __restrict__ Al,
                 const __nv_bfloat16* __restrict__ Bh, const __nv_bfloat16* __restrict__ Bl,
                 const float* __restrict__ bias0, const float* __restrict__ bias1,
                 __nv_bfloat16* __restrict__ outh, __nv_bfloat16* __restrict__ outl,
                 float* __restrict__ outf)
{
    constexpr int SA = 40;
    constexpr int SB = 136;
    constexpr int NB = NCOLS / 128;
    constexpr int GROUP_M = 16;
    extern __shared__ char smem_raw[];
    __nv_bfloat16* sA = (__nv_bfloat16*)smem_raw;
    __nv_bfloat16* sB = sA + 2 * 2 * 128 * SA;

    int bid = blockIdx.x;
    int gsz = GROUP_M * NB;
    int grp = bid / gsz;
    int rem = bid - grp * gsz;
    int bm  = grp * GROUP_M + (rem % GROUP_M);
    int bn  = rem / GROUP_M;

    int tid = threadIdx.x, lane = tid & 31, wid = tid >> 5;
    int wm = wid & 3, wn = wid >> 2;
    const int arow = tid >> 2, acol8 = (tid & 3) * 8;
    const int brow = tid >> 4, bcol8 = (tid & 15) * 8;

    auto load_stage = [&](int st, int k0) {
        __nv_bfloat16* dAh = sA + st * (2 * 128 * SA);
        __nv_bfloat16* dAl = dAh + 128 * SA;
        __nv_bfloat16* dBh = sB + st * (2 * 32 * SB);
        __nv_bfloat16* dBl = dBh + 32 * SB;
        size_t ga = (size_t)(bm * 128 + arow) * KD + k0 + acol8;
        cp16(dAh + arow * SA + acol8,        Ah + ga);
        cp16(dAh + (arow + 64) * SA + acol8, Ah + ga + (size_t)64 * KD);
        cp16(dAl + arow * SA + acol8,        Al + ga);
        cp16(dAl + (arow + 64) * SA + acol8, Al + ga + (size_t)64 * KD);
        size_t gb = (size_t)(k0 + brow) * NCOLS + bn * 128 + bcol8;
        cp16(dBh + brow * SB + bcol8,        Bh + gb);
        cp16(dBh + (brow + 16) * SB + bcol8, Bh + gb + (size_t)16 * NCOLS);
        cp16(dBl + brow * SB + bcol8,        Bl + gb);
        cp16(dBl + (brow + 16) * SB + bcol8, Bl + gb + (size_t)16 * NCOLS);
    };

    float acc[2][8][4];
    #pragma unroll
    for (int a = 0; a < 2; a++)
        #pragma unroll
        for (int b = 0; b < 8; b++)
            #pragma unroll
            for (int c = 0; c < 4; c++) acc[a][b][c] = 0.f;

    load_stage(0, 0);
    cp_commit();

    for (int kt = 0; kt < KD / 32; kt++) {
        if (kt + 1 < KD / 32) {
            load_stage((kt + 1) & 1, (kt + 1) * 32);
            cp_commit();
            cp_wait<1>();
        } else {
            cp_wait<0>();
        }
        __syncthreads();

        const __nv_bfloat16* cAh = sA + (kt & 1) * (2 * 128 * SA);
        const __nv_bfloat16* cAl = cAh + 128 * SA;
        const __nv_bfloat16* cBh = sB + (kt & 1) * (2 * 32 * SB);
        const __nv_bfloat16* cBl = cBh + 32 * SB;

        #pragma unroll
        for (int kk = 0; kk < 2; kk++) {
            uint32_t ah0[4], ah1[4], al0[4], al1[4];
            int ar = wm * 32 + (lane & 15);
            int ac = kk * 16 + (lane >> 4) * 8;
            ldsm4(ah0, cAh + ar * SA + ac);
            ldsm4(ah1, cAh + (ar + 16) * SA + ac);
            ldsm4(al0, cAl + ar * SA + ac);
            ldsm4(al1, cAl + (ar + 16) * SA + ac);
            int br = kk * 16 + (lane & 15);
            #pragma unroll
            for (int nj2 = 0; nj2 < 4; nj2++) {
                int bc = wn * 64 + nj2 * 16 + (lane >> 4) * 8;
                uint32_t bh[4], bl[4];
                ldsm4t(bh, cBh + br * SB + bc);
                ldsm4t(bl, cBl + br * SB + bc);
                #pragma unroll
                for (int t = 0; t < 2; t++) {
                    int nj = nj2 * 2 + t;
                    mma_bf16(acc[0][nj], ah0, bh + 2 * t);
                    mma_bf16(acc[0][nj], ah0, bl + 2 * t);
                    mma_bf16(acc[0][nj], al0, bh + 2 * t);
                    mma_bf16(acc[1][nj], ah1, bh + 2 * t);
                    mma_bf16(acc[1][nj], ah1, bl + 2 * t);
                    mma_bf16(acc[1][nj], al1, bh + 2 * t);
                }
            }
        }
        __syncthreads();
    }

    int row0 = bm * 128 + wm * 32 + (lane >> 2);
    int col0 = bn * 128 + wn * 64 + (lane & 3) * 2;
    #pragma unroll
    for (int mi = 0; mi < 2; mi++) {
        int ra = row0 + mi * 16;
        #pragma unroll
        for (int nj = 0; nj < 8; nj++) {
            int col = col0 + nj * 8;
            if (MODE == 1) {
                float b0, b1; float sc0, sc1;
                if (col < 512) { b0 = bias0[col]; b1 = bias0[col + 1]; sc0 = SCALE_Q; sc1 = SCALE_Q; }
                else { b0 = bias1[col - 512]; b1 = bias1[col - 511]; sc0 = 1.f; sc1 = 1.f; }
                size_t g0 = (size_t)ra * NCOLS + col;
                store_split2(outh + g0, outl + g0,
                             (acc[mi][nj][0] + b0) * sc0, (acc[mi][nj][1] + b1) * sc1);
                size_t g1 = (size_t)(ra + 8) * NCOLS + col;
                store_split2(outh + g1, outl + g1,
                             (acc[mi][nj][2] + b0) * sc0, (acc[mi][nj][3] + b1) * sc1);
            } else {
                float b0 = bias0[col], b1 = bias0[col + 1];
                float2 v01 = make_float2(acc[mi][nj][0] + b0, acc[mi][nj][1] + b1);
                float2 v23 = make_float2(acc[mi][nj][2] + b0, acc[mi][nj][3] + b1);
                *(float2*)&outf[(size_t)ra * NCOLS + col]       = v01;
                *(float2*)&outf[(size_t)(ra + 8) * NCOLS + col] = v23;
            }
        }
    }
}

// ------------------ tensor-core attention (split-bf16 MMA) -----------------
// 1 CTA (4 warps) per (window, head). Warp wr owns rows wr*16..wr*16+15.
// S = QK^T via 3-split MMA; exact fp32 softmax on fragments; attn stored as
// float2 from fragments; P split hi/lo in-register, reused as PV A operand.
__global__ __launch_bounds__(128)
void attn_mma_kernel(const __nv_bfloat16* __restrict__ qkvh,
                     const __nv_bfloat16* __restrict__ qkvl,
                     const float* __restrict__ table,
                     const int* __restrict__ relidx,
                     float* __restrict__ attn_out,
                     __nv_bfloat16* __restrict__ oh, __nv_bfloat16* __restrict__ ol)
{
    constexpr int SQ = 40;                   // padded bf16 stride (conflict-free ldsm)
    extern __shared__ char smraw[];
    __nv_bfloat16* sQK = (__nv_bfloat16*)smraw;              // 6 x [64*SQ]
    float*   sTab = (float*)(smraw + 6 * 64 * SQ * 2);       // 232 floats
    uint8_t* sIdx = (uint8_t*)(sTab + 232);                  // 4096 B

    const int w = blockIdx.x >> 4, h = blockIdx.x & 15;
    const int tid = threadIdx.x, lane = tid & 31, wr = tid >> 5;
    const size_t rowbase = (size_t)(w * 64) * NC1;

    // async load Q/K/V hi+lo tiles [64 x 32] each (1536 cp16 total)
    #pragma unroll
    for (int it = 0; it < 12; it++) {
        int e = tid + it * 128;
        int a = e >> 8;                       // 0..5 : Qh Ql Kh Kl Vh Vl
        int rem = e & 255;
        int i = rem >> 2, c = (rem & 3) * 8;
        const __nv_bfloat16* src = (a & 1) ? qkvl : qkvh;
        size_t g = rowbase + (size_t)i * NC1 + h * 32 + (a >> 1) * 512 + c;
        cp16(sQK + a * (64 * SQ) + i * SQ + c, src + g);
    }
    cp_commit();
    for (int t = tid; t < 4096; t += 128) sIdx[t] = (uint8_t)relidx[t];
    for (int t = tid; t < 225;  t += 128) sTab[t] = table[t * NHEADS + h];
    cp_wait<0>();
    __syncthreads();

    const __nv_bfloat16* sQh = sQK;
    const __nv_bfloat16* sQl = sQK + 1 * (64 * SQ);
    const __nv_bfloat16* sKh = sQK + 2 * (64 * SQ);
    const __nv_bfloat16* sKl = sQK + 3 * (64 * SQ);
    const __nv_bfloat16* sVh = sQK + 4 * (64 * SQ);
    const __nv_bfloat16* sVl = sQK + 5 * (64 * SQ);

    const int r0 = wr * 16;

    // ---- S = Q K^T ----
    uint32_t qh[2][4], ql[2][4];
    #pragma unroll
    for (int kc = 0; kc < 2; kc++) {
        int ad = (r0 + (lane & 15)) * SQ + kc * 16 + (lane >> 4) * 8;
        ldsm4(qh[kc], sQh + ad);
        ldsm4(ql[kc], sQl + ad);
    }
    float acc[8][4];
    #pragma unroll
    for (int j = 0; j < 8; j++)
        #pragma unroll
        for (int c = 0; c < 4; c++) acc[j][c] = 0.f;

    #pragma unroll
    for (int kc = 0; kc < 2; kc++) {
        #pragma unroll
        for (int jj = 0; jj < 4; jj++) {
            // non-trans ldsm on K[token][dim] gives col-major B = K^T fragments
            int row = jj * 16 + (lane & 7) + ((lane >> 4) & 1) * 8;
            int col = kc * 16 + ((lane >> 3) & 1) * 8;
            uint32_t kh[4], kl[4];
            ldsm4(kh, sKh + row * SQ + col);
            ldsm4(kl, sKl + row * SQ + col);
            mma_bf16(acc[2 * jj],     qh[kc], kh);
            mma_bf16(acc[2 * jj],     qh[kc], kl);
            mma_bf16(acc[2 * jj],     ql[kc], kh);
            mma_bf16(acc[2 * jj + 1], qh[kc], kh + 2);
            mma_bf16(acc[2 * jj + 1], qh[kc], kl + 2);
            mma_bf16(acc[2 * jj + 1], ql[kc], kh + 2);
        }
    }

    // ---- bias + exact softmax on fragments ----
    const int rA = r0 + (lane >> 2), rB = rA + 8;
    const int cb = (lane & 3) * 2;
    float mA = -1e30f, mB = -1e30f;
    #pragma unroll
    for (int j = 0; j < 8; j++) {
        int c0 = j * 8 + cb;
        acc[j][0] += sTab[sIdx[rA * 64 + c0]];
        acc[j][1] += sTab[sIdx[rA * 64 + c0 + 1]];
        acc[j][2] += sTab[sIdx[rB * 64 + c0]];
        acc[j][3] += sTab[sIdx[rB * 64 + c0 + 1]];
        mA = fmaxf(mA, fmaxf(acc[j][0], acc[j][1]));
        mB = fmaxf(mB, fmaxf(acc[j][2], acc[j][3]));
    }
    mA = fmaxf(mA, __shfl_xor_sync(0xffffffffu, mA, 1));
    mA = fmaxf(mA, __shfl_xor_sync(0xffffffffu, mA, 2));
    mB = fmaxf(mB, __shfl_xor_sync(0xffffffffu, mB, 1));
    mB = fmaxf(mB, __shfl_xor_sync(0xffffffffu, mB, 2));
    float sA = 0.f, sB = 0.f;
    #pragma unroll
    for (int j = 0; j < 8; j++) {
        acc[j][0] = __expf(acc[j][0] - mA);
        acc[j][1] = __expf(acc[j][1] - mA);
        acc[j][2] = __expf(acc[j][2] - mB);
        acc[j][3] = __expf(acc[j][3] - mB);
        sA += acc[j][0] + acc[j][1];
        sB += acc[j][2] + acc[j][3];
    }
    sA += __shfl_xor_sync(0xffffffffu, sA, 1);
    sA += __shfl_xor_sync(0xffffffffu, sA, 2);
    sB += __shfl_xor_sync(0xffffffffu, sB, 1);
    sB += __shfl_xor_sync(0xffffffffu, sB, 2);
    const float invA = 1.f / sA, invB = 1.f / sB;

    // ---- P: store attn, pack split-bf16 A-fragments ----
    uint32_t ph[4][4], pl[4][4];
    const size_t abase = (size_t)blockIdx.x * 64;
    #pragma unroll
    for (int j = 0; j < 8; j++) {
        float p0 = acc[j][0] * invA, p1 = acc[j][1] * invA;
        float p2 = acc[j][2] * invB, p3 = acc[j][3] * invB;
        *(float2*)&attn_out[(abase + rA) * 64 + j * 8 + cb] = make_float2(p0, p1);
        *(float2*)&attn_out[(abase + rB) * 64 + j * 8 + cb] = make_float2(p2, p3);
        int t = j >> 1, s = (j & 1) * 2;       // a-frag regs: even tile -> 0,1 ; odd -> 2,3
        pack_split(p0, p1, ph[t][s + 0], pl[t][s + 0]);
        pack_split(p2, p3, ph[t][s + 1], pl[t][s + 1]);
    }

    // ---- O = P V ----
    float o[4][4];
    #pragma unroll
    for (int nj = 0; nj < 4; nj++)
        #pragma unroll
        for (int c = 0; c < 4; c++) o[nj][c] = 0.f;
    #pragma unroll
    for (int kc = 0; kc < 4; kc++) {
        #pragma unroll
        for (int vb = 0; vb < 2; vb++) {
            int ad = (kc * 16 + (lane & 15)) * SQ + vb * 16 + (lane >> 4) * 8;
            uint32_t vh[4], vl[4];
            ldsm4t(vh, sVh + ad);
            ldsm4t(vl, sVl + ad);
            mma_bf16(o[vb * 2],     ph[kc], vh);
            mma_bf16(o[vb * 2],     ph[kc], vl);
            mma_bf16(o[vb * 2],     pl[kc], vh);
            mma_bf16(o[vb * 2 + 1], ph[kc], vh + 2);
            mma_bf16(o[vb * 2 + 1], ph[kc], vl + 2);
            mma_bf16(o[vb * 2 + 1], pl[kc], vh + 2);
        }
    }

    // ---- store O (split-bf16, token-major [T x 512]) ----
    #pragma unroll
    for (int nj = 0; nj < 4; nj++) {
        int col = h * 32 + nj * 8 + cb;
        size_t gA = (size_t)(w * 64 + rA) * KD + col;
        size_t gB = (size_t)(w * 64 + rB) * KD + col;
        store_split2(oh + gA, ol + gA, o[nj][0], o[nj][1]);
        store_split2(oh + gB, ol + gB, o[nj][2], o[nj][3]);
    }
}

// ------------------------------- launcher ----------------------------------
extern "C" void kernel_launch(void* const* d_in, const int* in_sizes, int n_in,
                              void* d_out, int out_size) {
    const float* q      = (const float*)d_in[0];
    const float* wq     = (const float*)d_in[1];
    const float* bq     = (const float*)d_in[2];
    const float* wkv    = (const float*)d_in[3];
    const float* bkv    = (const float*)d_in[4];
    const float* wproj  = (const float*)d_in[5];
    const float* bproj  = (const float*)d_in[6];
    const float* table  = (const float*)d_in[7];
    const int*   relidx = (const int*)d_in[8];

    float* out_x    = (float*)d_out;
    float* out_attn = out_x + (size_t)TOKENS * KD;

    __nv_bfloat16 *q_hi, *q_lo, *w1_hi, *w1_lo, *w3_hi, *w3_lo;
    __nv_bfloat16 *qkv_hi, *qkv_lo, *o_hi, *o_lo;
    cudaGetSymbolAddress((void**)&q_hi,   g_q_hi);
    cudaGetSymbolAddress((void**)&q_lo,   g_q_lo);
    cudaGetSymbolAddress((void**)&w1_hi,  g_w1_hi);
    cudaGetSymbolAddress((void**)&w1_lo,  g_w1_lo);
    cudaGetSymbolAddress((void**)&w3_hi,  g_w3_hi);
    cudaGetSymbolAddress((void**)&w3_lo,  g_w3_lo);
    cudaGetSymbolAddress((void**)&qkv_hi, g_qkv_hi);
    cudaGetSymbolAddress((void**)&qkv_lo, g_qkv_lo);
    cudaGetSymbolAddress((void**)&o_hi,   g_o_hi);
    cudaGetSymbolAddress((void**)&o_lo,   g_o_lo);

    const int smem_gemm = (2 * 2 * 128 * 40 + 2 * 2 * 32 * 136) * 2;
    const int smem_attn = 6 * 64 * 40 * 2 + 232 * 4 + 4096;   // 35744
    cudaFuncSetAttribute(gemm_kernel<NC1, 1>, cudaFuncAttributeMaxDynamicSharedMemorySize, smem_gemm);
    cudaFuncSetAttribute(gemm_kernel<KD, 3>,  cudaFuncAttributeMaxDynamicSharedMemorySize, smem_gemm);
    cudaFuncSetAttribute(attn_mma_kernel, cudaFuncAttributeMaxDynamicSharedMemorySize, smem_attn);

    split_f32_kernel<<<(TOKENS * KD) / 256, 256>>>(q, q_hi, q_lo, TOKENS * KD);
    split_w1_kernel<<<(KD * NC1) / 256, 256>>>(wq, wkv);
    split_f32_kernel<<<(KD * KD) / 256, 256>>>(wproj, w3_hi, w3_lo, KD * KD);

    gemm_kernel<NC1, 1><<<(TOKENS / 128) * (NC1 / 128), 256, smem_gemm>>>(
        q_hi, q_lo, w1_hi, w1_lo, bq, bkv, qkv_hi, qkv_lo, nullptr);

    attn_mma_kernel<<<1024 * NHEADS, 128, smem_attn>>>(
        qkv_hi, qkv_lo, table, relidx, out_attn, o_hi, o_lo);

    gemm_kernel<KD, 3><<<(TOKENS / 128) * (KD / 128), 256, smem_gemm>>>(
        o_hi, o_lo, w3_hi, w3_lo, bproj, nullptr, nullptr, nullptr, out_x);
}

// round 5
// speedup vs baseline: 1.3126x; 1.0036x over previous
#include <cuda_runtime.h>
#include <cuda_bf16.h>
#include <stdint.h>

#define TOKENS   65536
#define KD       512
#define NC1      1536
#define NHEADS   16
#define SCALE_Q  0.17677669529663688f

// ------------------------- device scratch (static) -------------------------
__device__ __nv_bfloat16 g_q_hi  [TOKENS * KD];
__device__ __nv_bfloat16 g_q_lo  [TOKENS * KD];
__device__ __nv_bfloat16 g_w1_hi [KD * NC1];
__device__ __nv_bfloat16 g_w1_lo [KD * NC1];
__device__ __nv_bfloat16 g_w3_hi [KD * KD];
__device__ __nv_bfloat16 g_w3_lo [KD * KD];
__device__ __nv_bfloat16 g_qkv_hi[(size_t)TOKENS * NC1];
__device__ __nv_bfloat16 g_qkv_lo[(size_t)TOKENS * NC1];
__device__ __nv_bfloat16 g_o_hi  [TOKENS * KD];
__device__ __nv_bfloat16 g_o_lo  [TOKENS * KD];

// ------------------------------ PTX helpers --------------------------------
__device__ __forceinline__ uint32_t smem_u32(const void* p) {
    return (uint32_t)__cvta_generic_to_shared(p);
}
__device__ __forceinline__ void cp16(void* s, const void* g) {
    asm volatile("cp.async.cg.shared.global [%0], [%1], 16;\n"
                 :: "r"(smem_u32(s)), "l"(g));
}
__device__ __forceinline__ void cp_commit() { asm volatile("cp.async.commit_group;\n"); }
template<int N> __device__ __forceinline__ void cp_wait() {
    asm volatile("cp.async.wait_group %0;\n" :: "n"(N));
}
__device__ __forceinline__ void ldsm4(uint32_t r[4], const void* p) {
    asm volatile("ldmatrix.sync.aligned.m8n8.x4.shared.b16 {%0,%1,%2,%3}, [%4];\n"
        : "=r"(r[0]), "=r"(r[1]), "=r"(r[2]), "=r"(r[3]) : "r"(smem_u32(p)));
}
__device__ __forceinline__ void ldsm4t(uint32_t r[4], const void* p) {
    asm volatile("ldmatrix.sync.aligned.m8n8.x4.trans.shared.b16 {%0,%1,%2,%3}, [%4];\n"
        : "=r"(r[0]), "=r"(r[1]), "=r"(r[2]), "=r"(r[3]) : "r"(smem_u32(p)));
}
__device__ __forceinline__ void mma_bf16(float c[4], const uint32_t a[4], const uint32_t b[2]) {
    asm volatile(
        "mma.sync.aligned.m16n8k16.row.col.f32.bf16.bf16.f32 "
        "{%0,%1,%2,%3}, {%4,%5,%6,%7}, {%8,%9}, {%0,%1,%2,%3};\n"
        : "+f"(c[0]), "+f"(c[1]), "+f"(c[2]), "+f"(c[3])
        : "r"(a[0]), "r"(a[1]), "r"(a[2]), "r"(a[3]), "r"(b[0]), "r"(b[1]));
}
__device__ __forceinline__ void store_split2(__nv_bfloat16* ph, __nv_bfloat16* pl,
                                             float v0, float v1) {
    __nv_bfloat16 h0 = __float2bfloat16(v0);
    __nv_bfloat16 h1 = __float2bfloat16(v1);
    __nv_bfloat16 l0 = __float2bfloat16(v0 - __bfloat162float(h0));
    __nv_bfloat16 l1 = __float2bfloat16(v1 - __bfloat162float(h1));
    *reinterpret_cast<__nv_bfloat162*>(ph) = __halves2bfloat162(h0, h1);
    *reinterpret_cast<__nv_bfloat162*>(pl) = __halves2bfloat162(l0, l1);
}
__device__ __forceinline__ void pack_split(float a, float b, uint32_t& hi, uint32_t& lo) {
    __nv_bfloat16 ah = __float2bfloat16(a);
    __nv_bfloat16 bh = __float2bfloat16(b);
    __nv_bfloat162 h2 = __halves2bfloat162(ah, bh);
    __nv_bfloat162 l2 = __halves2bfloat162(
        __float2bfloat16(a - __bfloat162float(ah)),
        __float2bfloat16(b - __bfloat162float(bh)));
    hi = *reinterpret_cast<uint32_t*>(&h2);
    lo = *reinterpret_cast<uint32_t*>(&l2);
}

// ------------------------------ prep kernels -------------------------------
__global__ void split_f32_kernel(const float* __restrict__ src,
                                 __nv_bfloat16* __restrict__ hi,
                                 __nv_bfloat16* __restrict__ lo, int n) {
    int i = blockIdx.x * blockDim.x + threadIdx.x;
    if (i >= n) return;
    float v = src[i];
    __nv_bfloat16 h = __float2bfloat16(v);
    hi[i] = h;
    lo[i] = __float2bfloat16(v - __bfloat162float(h));
}

__global__ void split_w1_kernel(const float* __restrict__ wq,
                                const float* __restrict__ wkv) {
    int i = blockIdx.x * blockDim.x + threadIdx.x;
    if (i >= KD * NC1) return;
    int k = i / NC1, n = i - k * NC1;
    float v = (n < KD) ? wq[k * KD + n] : wkv[k * 1024 + (n - KD)];
    __nv_bfloat16 h = __float2bfloat16(v);
    g_w1_hi[i] = h;
    g_w1_lo[i] = __float2bfloat16(v - __bfloat162float(h));
}

// ---------------- split-bf16 GEMM, 128x128x32 tiles, 3-stage ---------------
// MODE 1: QKV epilogue (bias + Q scale, split-bf16 out). MODE 3: fp32 out.
template<int NCOLS, int MODE>
__global__ __launch_bounds__(256, 2)
void gemm_kernel(const __nv_bfloat16* __restrict__ Ah, const __nv_bfloat16* __restrict__ Al,
                 const __nv_bfloat16* __restrict__ Bh, const __nv_bfloat16* __restrict__ Bl,
                 const float* __restrict__ bias0, const float* __restrict__ bias1,
                 __nv_bfloat16* __restrict__ outh, __nv_bfloat16* __restrict__ outl,
                 float* __restrict__ outf)
{
    constexpr int SA = 40;
    constexpr int SB = 136;
    constexpr int NB = NCOLS / 128;
    constexpr int GROUP_M = 16;
    constexpr int STAGE = 2 * 128 * SA + 2 * 32 * SB;   // 18944 bf16 elems / stage
    constexpr int KITER = KD / 32;                      // 16

    extern __shared__ char smem_raw[];
    __nv_bfloat16* smem = (__nv_bfloat16*)smem_raw;

    int bid = blockIdx.x;
    int gsz = GROUP_M * NB;
    int grp = bid / gsz;
    int rem = bid - grp * gsz;
    int bm  = grp * GROUP_M + (rem % GROUP_M);
    int bn  = rem / GROUP_M;

    int tid = threadIdx.x, lane = tid & 31, wid = tid >> 5;
    int wm = wid & 3, wn = wid >> 2;
    const int arow = tid >> 2, acol8 = (tid & 3) * 8;
    const int brow = tid >> 4, bcol8 = (tid & 15) * 8;

    auto load_stage = [&](__nv_bfloat16* sb, int k0) {
        __nv_bfloat16* dAh = sb;
        __nv_bfloat16* dAl = sb + 128 * SA;
        __nv_bfloat16* dBh = sb + 2 * 128 * SA;
        __nv_bfloat16* dBl = dBh + 32 * SB;
        size_t ga = (size_t)(bm * 128 + arow) * KD + k0 + acol8;
        cp16(dAh + arow * SA + acol8,        Ah + ga);
        cp16(dAh + (arow + 64) * SA + acol8, Ah + ga + (size_t)64 * KD);
        cp16(dAl + arow * SA + acol8,        Al + ga);
        cp16(dAl + (arow + 64) * SA + acol8, Al + ga + (size_t)64 * KD);
        size_t gb = (size_t)(k0 + brow) * NCOLS + bn * 128 + bcol8;
        cp16(dBh + brow * SB + bcol8,        Bh + gb);
        cp16(dBh + (brow + 16) * SB + bcol8, Bh + gb + (size_t)16 * NCOLS);
        cp16(dBl + brow * SB + bcol8,        Bl + gb);
        cp16(dBl + (brow + 16) * SB + bcol8, Bl + gb + (size_t)16 * NCOLS);
    };

    float acc[2][8][4];
    #pragma unroll
    for (int a = 0; a < 2; a++)
        #pragma unroll
        for (int b = 0; b < 8; b++)
            #pragma unroll
            for (int c = 0; c < 4; c++) acc[a][b][c] = 0.f;

    // 3-stage rotation: bc = compute, bnx = next compute, blw = load target
    __nv_bfloat16* bc  = smem;
    __nv_bfloat16* bnx = smem + STAGE;
    __nv_bfloat16* blw = smem + 2 * STAGE;

    load_stage(bc, 0);
    cp_commit();
    load_stage(bnx, 32);
    cp_commit();

    #pragma unroll 1
    for (int kt = 0; kt < KITER; kt++) {
        cp_wait<1>();
        __syncthreads();
        // load target = stage computed at kt-1; the barrier above orders it.
        if (kt + 2 < KITER) load_stage(blw, (kt + 2) * 32);
        cp_commit();

        const __nv_bfloat16* cAh = bc;
        const __nv_bfloat16* cAl = bc + 128 * SA;
        const __nv_bfloat16* cBh = bc + 2 * 128 * SA;
        const __nv_bfloat16* cBl = cBh + 32 * SB;

        #pragma unroll
        for (int kk = 0; kk < 2; kk++) {
            uint32_t ah0[4], ah1[4], al0[4], al1[4];
            int ar = wm * 32 + (lane & 15);
            int ac = kk * 16 + (lane >> 4) * 8;
            ldsm4(ah0, cAh + ar * SA + ac);
            ldsm4(ah1, cAh + (ar + 16) * SA + ac);
            ldsm4(al0, cAl + ar * SA + ac);
            ldsm4(al1, cAl + (ar + 16) * SA + ac);
            int br = kk * 16 + (lane & 15);
            #pragma unroll
            for (int nj2 = 0; nj2 < 4; nj2++) {
                int bcc = wn * 64 + nj2 * 16 + (lane >> 4) * 8;
                uint32_t bh[4], bl[4];
                ldsm4t(bh, cBh + br * SB + bcc);
                ldsm4t(bl, cBl + br * SB + bcc);
                #pragma unroll
                for (int t = 0; t < 2; t++) {
                    int nj = nj2 * 2 + t;
                    // interleave acc0/acc1 chains (RAW distance 2)
                    mma_bf16(acc[0][nj], ah0, bh + 2 * t);
                    mma_bf16(acc[1][nj], ah1, bh + 2 * t);
                    mma_bf16(acc[0][nj], ah0, bl + 2 * t);
                    mma_bf16(acc[1][nj], ah1, bl + 2 * t);
                    mma_bf16(acc[0][nj], al0, bh + 2 * t);
                    mma_bf16(acc[1][nj], al1, bh + 2 * t);
                }
            }
        }
        // rotate stages
        __nv_bfloat16* tmp = bc;
        bc = bnx; bnx = blw; blw = tmp;
    }

    int row0 = bm * 128 + wm * 32 + (lane >> 2);
    int col0 = bn * 128 + wn * 64 + (lane & 3) * 2;
    #pragma unroll
    for (int mi = 0; mi < 2; mi++) {
        int ra = row0 + mi * 16;
        #pragma unroll
        for (int nj = 0; nj < 8; nj++) {
            int col = col0 + nj * 8;
            if (MODE == 1) {
                float b0, b1; float sc0, sc1;
                if (col < 512) { b0 = bias0[col]; b1 = bias0[col + 1]; sc0 = SCALE_Q; sc1 = SCALE_Q; }
                else { b0 = bias1[col - 512]; b1 = bias1[col - 511]; sc0 = 1.f; sc1 = 1.f; }
                size_t g0 = (size_t)ra * NCOLS + col;
                store_split2(outh + g0, outl + g0,
                             (acc[mi][nj][0] + b0) * sc0, (acc[mi][nj][1] + b1) * sc1);
                size_t g1 = (size_t)(ra + 8) * NCOLS + col;
                store_split2(outh + g1, outl + g1,
                             (acc[mi][nj][2] + b0) * sc0, (acc[mi][nj][3] + b1) * sc1);
            } else {
                float b0 = bias0[col], b1 = bias0[col + 1];
                float2 v01 = make_float2(acc[mi][nj][0] + b0, acc[mi][nj][1] + b1);
                float2 v23 = make_float2(acc[mi][nj][2] + b0, acc[mi][nj][3] + b1);
                *(float2*)&outf[(size_t)ra * NCOLS + col]       = v01;
                *(float2*)&outf[(size_t)(ra + 8) * NCOLS + col] = v23;
            }
        }
    }
}

// ------------------ tensor-core attention (split-bf16 MMA) -----------------
__global__ __launch_bounds__(128)
void attn_mma_kernel(const __nv_bfloat16* __restrict__ qkvh,
                     const __nv_bfloat16* __restrict__ qkvl,
                     const float* __restrict__ table,
                     const int* __restrict__ relidx,
                     float* __restrict__ attn_out,
                     __nv_bfloat16* __restrict__ oh, __nv_bfloat16* __restrict__ ol)
{
    constexpr int SQ = 40;
    extern __shared__ char smraw[];
    __nv_bfloat16* sQK = (__nv_bfloat16*)smraw;              // 6 x [64*SQ]
    float*   sTab = (float*)(smraw + 6 * 64 * SQ * 2);       // 232 floats
    uint8_t* sIdx = (uint8_t*)(sTab + 232);                  // 4096 B

    const int w = blockIdx.x >> 4, h = blockIdx.x & 15;
    const int tid = threadIdx.x, lane = tid & 31, wr = tid >> 5;
    const size_t rowbase = (size_t)(w * 64) * NC1;

    #pragma unroll
    for (int it = 0; it < 12; it++) {
        int e = tid + it * 128;
        int a = e >> 8;
        int rem = e & 255;
        int i = rem >> 2, c = (rem & 3) * 8;
        const __nv_bfloat16* src = (a & 1) ? qkvl : qkvh;
        size_t g = rowbase + (size_t)i * NC1 + h * 32 + (a >> 1) * 512 + c;
        cp16(sQK + a * (64 * SQ) + i * SQ + c, src + g);
    }
    cp_commit();
    for (int t = tid; t < 4096; t += 128) sIdx[t] = (uint8_t)relidx[t];
    for (int t = tid; t < 225;  t += 128) sTab[t] = table[t * NHEADS + h];
    cp_wait<0>();
    __syncthreads();

    const __nv_bfloat16* sQh = sQK;
    const __nv_bfloat16* sQl = sQK + 1 * (64 * SQ);
    const __nv_bfloat16* sKh = sQK + 2 * (64 * SQ);
    const __nv_bfloat16* sKl = sQK + 3 * (64 * SQ);
    const __nv_bfloat16* sVh = sQK + 4 * (64 * SQ);
    const __nv_bfloat16* sVl = sQK + 5 * (64 * SQ);

    const int r0 = wr * 16;

    uint32_t qh[2][4], ql[2][4];
    #pragma unroll
    for (int kc = 0; kc < 2; kc++) {
        int ad = (r0 + (lane & 15)) * SQ + kc * 16 + (lane >> 4) * 8;
        ldsm4(qh[kc], sQh + ad);
        ldsm4(ql[kc], sQl + ad);
    }
    float acc[8][4];
    #pragma unroll
    for (int j = 0; j < 8; j++)
        #pragma unroll
        for (int c = 0; c < 4; c++) acc[j][c] = 0.f;

    #pragma unroll
    for (int kc = 0; kc < 2; kc++) {
        #pragma unroll
        for (int jj = 0; jj < 4; jj++) {
            int row = jj * 16 + (lane & 7) + ((lane >> 4) & 1) * 8;
            int col = kc * 16 + ((lane >> 3) & 1) * 8;
            uint32_t kh[4], kl[4];
            ldsm4(kh, sKh + row * SQ + col);
            ldsm4(kl, sKl + row * SQ + col);
            mma_bf16(acc[2 * jj],     qh[kc], kh);
            mma_bf16(acc[2 * jj + 1], qh[kc], kh + 2);
            mma_bf16(acc[2 * jj],     qh[kc], kl);
            mma_bf16(acc[2 * jj + 1], qh[kc], kl + 2);
            mma_bf16(acc[2 * jj],     ql[kc], kh);
            mma_bf16(acc[2 * jj + 1], ql[kc], kh + 2);
        }
    }

    const int rA = r0 + (lane >> 2), rB = rA + 8;
    const int cb = (lane & 3) * 2;
    float mA = -1e30f, mB = -1e30f;
    #pragma unroll
    for (int j = 0; j < 8; j++) {
        int c0 = j * 8 + cb;
        acc[j][0] += sTab[sIdx[rA * 64 + c0]];
        acc[j][1] += sTab[sIdx[rA * 64 + c0 + 1]];
        acc[j][2] += sTab[sIdx[rB * 64 + c0]];
        acc[j][3] += sTab[sIdx[rB * 64 + c0 + 1]];
        mA = fmaxf(mA, fmaxf(acc[j][0], acc[j][1]));
        mB = fmaxf(mB, fmaxf(acc[j][2], acc[j][3]));
    }
    mA = fmaxf(mA, __shfl_xor_sync(0xffffffffu, mA, 1));
    mA = fmaxf(mA, __shfl_xor_sync(0xffffffffu, mA, 2));
    mB = fmaxf(mB, __shfl_xor_sync(0xffffffffu, mB, 1));
    mB = fmaxf(mB, __shfl_xor_sync(0xffffffffu, mB, 2));
    float sA = 0.f, sB = 0.f;
    #pragma unroll
    for (int j = 0; j < 8; j++) {
        acc[j][0] = __expf(acc[j][0] - mA);
        acc[j][1] = __expf(acc[j][1] - mA);
        acc[j][2] = __expf(acc[j][2] - mB);
        acc[j][3] = __expf(acc[j][3] - mB);
        sA += acc[j][0] + acc[j][1];
        sB += acc[j][2] + acc[j][3];
    }
    sA += __shfl_xor_sync(0xffffffffu, sA, 1);
    sA += __shfl_xor_sync(0xffffffffu, sA, 2);
    sB += __shfl_xor_sync(0xffffffffu, sB, 1);
    sB += __shfl_xor_sync(0xffffffffu, sB, 2);
    const float invA = 1.f / sA, invB = 1.f / sB;

    uint32_t ph[4][4], pl[4][4];
    const size_t abase = (size_t)blockIdx.x * 64;
    #pragma unroll
    for (int j = 0; j < 8; j++) {
        float p0 = acc[j][0] * invA, p1 = acc[j][1] * invA;
        float p2 = acc[j][2] * invB, p3 = acc[j][3] * invB;
        *(float2*)&attn_out[(abase + rA) * 64 + j * 8 + cb] = make_float2(p0, p1);
        *(float2*)&attn_out[(abase + rB) * 64 + j * 8 + cb] = make_float2(p2, p3);
        int t = j >> 1, s = (j & 1) * 2;
        pack_split(p0, p1, ph[t][s + 0], pl[t][s + 0]);
        pack_split(p2, p3, ph[t][s + 1], pl[t][s + 1]);
    }

    float o[4][4];
    #pragma unroll
    for (int nj = 0; nj < 4; nj++)
        #pragma unroll
        for (int c = 0; c < 4; c++) o[nj][c] = 0.f;
    #pragma unroll
    for (int kc = 0; kc < 4; kc++) {
        #pragma unroll
        for (int vb = 0; vb < 2; vb++) {
            int ad = (kc * 16 + (lane & 15)) * SQ + vb * 16 + (lane >> 4) * 8;
            uint32_t vh[4], vl[4];
            ldsm4t(vh, sVh + ad);
            ldsm4t(vl, sVl + ad);
            mma_bf16(o[vb * 2],     ph[kc], vh);
            mma_bf16(o[vb * 2 + 1], ph[kc], vh + 2);
            mma_bf16(o[vb * 2],     ph[kc], vl);
            mma_bf16(o[vb * 2 + 1], ph[kc], vl + 2);
            mma_bf16(o[vb * 2],     pl[kc], vh);
            mma_bf16(o[vb * 2 + 1], pl[kc], vh + 2);
        }
    }

    #pragma unroll
    for (int nj = 0; nj < 4; nj++) {
        int col = h * 32 + nj * 8 + cb;
        size_t gA = (size_t)(w * 64 + rA) * KD + col;
        size_t gB = (size_t)(w * 64 + rB) * KD + col;
        store_split2(oh + gA, ol + gA, o[nj][0], o[nj][1]);
        store_split2(oh + gB, ol + gB, o[nj][2], o[nj][3]);
    }
}

// ------------------------------- launcher ----------------------------------
extern "C" void kernel_launch(void* const* d_in, const int* in_sizes, int n_in,
                              void* d_out, int out_size) {
    const float* q      = (const float*)d_in[0];
    const float* wq     = (const float*)d_in[1];
    const float* bq     = (const float*)d_in[2];
    const float* wkv    = (const float*)d_in[3];
    const float* bkv    = (const float*)d_in[4];
    const float* wproj  = (const float*)d_in[5];
    const float* bproj  = (const float*)d_in[6];
    const float* table  = (const float*)d_in[7];
    const int*   relidx = (const int*)d_in[8];

    float* out_x    = (float*)d_out;
    float* out_attn = out_x + (size_t)TOKENS * KD;

    __nv_bfloat16 *q_hi, *q_lo, *w1_hi, *w1_lo, *w3_hi, *w3_lo;
    __nv_bfloat16 *qkv_hi, *qkv_lo, *o_hi, *o_lo;
    cudaGetSymbolAddress((void**)&q_hi,   g_q_hi);
    cudaGetSymbolAddress((void**)&q_lo,   g_q_lo);
    cudaGetSymbolAddress((void**)&w1_hi,  g_w1_hi);
    cudaGetSymbolAddress((void**)&w1_lo,  g_w1_lo);
    cudaGetSymbolAddress((void**)&w3_hi,  g_w3_hi);
    cudaGetSymbolAddress((void**)&w3_lo,  g_w3_lo);
    cudaGetSymbolAddress((void**)&qkv_hi, g_qkv_hi);
    cudaGetSymbolAddress((void**)&qkv_lo, g_qkv_lo);
    cudaGetSymbolAddress((void**)&o_hi,   g_o_hi);
    cudaGetSymbolAddress((void**)&o_lo,   g_o_lo);

    const int smem_gemm = 3 * (2 * 128 * 40 + 2 * 32 * 136) * 2;   // 113,664
    const int smem_attn = 6 * 64 * 40 * 2 + 232 * 4 + 4096;        // 35,744
    cudaFuncSetAttribute(gemm_kernel<NC1, 1>, cudaFuncAttributeMaxDynamicSharedMemorySize, smem_gemm);
    cudaFuncSetAttribute(gemm_kernel<KD, 3>,  cudaFuncAttributeMaxDynamicSharedMemorySize, smem_gemm);
    cudaFuncSetAttribute(attn_mma_kernel, cudaFuncAttributeMaxDynamicSharedMemorySize, smem_attn);

    split_f32_kernel<<<(TOKENS * KD) / 256, 256>>>(q, q_hi, q_lo, TOKENS * KD);
    split_w1_kernel<<<(KD * NC1) / 256, 256>>>(wq, wkv);
    split_f32_kernel<<<(KD * KD) / 256, 256>>>(wproj, w3_hi, w3_lo, KD * KD);

    gemm_kernel<NC1, 1><<<(TOKENS / 128) * (NC1 / 128), 256, smem_gemm>>>(
        q_hi, q_lo, w1_hi, w1_lo, bq, bkv, qkv_hi, qkv_lo, nullptr);

    attn_mma_kernel<<<1024 * NHEADS, 128, smem_attn>>>(
        qkv_hi, qkv_lo, table, relidx, out_attn, o_hi, o_lo);

    gemm_kernel<KD, 3><<<(TOKENS / 128) * (KD / 128), 256, smem_gemm>>>(
        o_hi, o_lo, w3_hi, w3_lo, bproj, nullptr, nullptr, nullptr, out_x);
}

// round 6
// speedup vs baseline: 1.7535x; 1.3359x over previous
#include <cuda_runtime.h>
#include <cuda_fp16.h>
#include <stdint.h>

#define TOKENS   65536
#define KD       512
#define NC1      1536
#define NHEADS   16
#define SCALE_Q  0.17677669529663688f

// ------------------------- device scratch (static) -------------------------
__device__ __half g_q_h  [TOKENS * KD];
__device__ __half g_w1_h [KD * NC1];
__device__ __half g_w1_l [KD * NC1];
__device__ __half g_w3_h [KD * KD];
__device__ __half g_w3_l [KD * KD];
__device__ __half g_qkv_h[(size_t)TOKENS * NC1];
__device__ __half g_qkv_l[(size_t)TOKENS * NC1];
__device__ __half g_o_h  [TOKENS * KD];

// ------------------------------ PTX helpers --------------------------------
__device__ __forceinline__ uint32_t smem_u32(const void* p) {
    return (uint32_t)__cvta_generic_to_shared(p);
}
__device__ __forceinline__ void cp16(void* s, const void* g) {
    asm volatile("cp.async.cg.shared.global [%0], [%1], 16;\n"
                 :: "r"(smem_u32(s)), "l"(g));
}
__device__ __forceinline__ void cp_commit() { asm volatile("cp.async.commit_group;\n"); }
template<int N> __device__ __forceinline__ void cp_wait() {
    asm volatile("cp.async.wait_group %0;\n" :: "n"(N));
}
__device__ __forceinline__ void ldsm4(uint32_t r[4], const void* p) {
    asm volatile("ldmatrix.sync.aligned.m8n8.x4.shared.b16 {%0,%1,%2,%3}, [%4];\n"
        : "=r"(r[0]), "=r"(r[1]), "=r"(r[2]), "=r"(r[3]) : "r"(smem_u32(p)));
}
__device__ __forceinline__ void ldsm4t(uint32_t r[4], const void* p) {
    asm volatile("ldmatrix.sync.aligned.m8n8.x4.trans.shared.b16 {%0,%1,%2,%3}, [%4];\n"
        : "=r"(r[0]), "=r"(r[1]), "=r"(r[2]), "=r"(r[3]) : "r"(smem_u32(p)));
}
__device__ __forceinline__ void mma_f16(float c[4], const uint32_t a[4], const uint32_t b[2]) {
    asm volatile(
        "mma.sync.aligned.m16n8k16.row.col.f32.f16.f16.f32 "
        "{%0,%1,%2,%3}, {%4,%5,%6,%7}, {%8,%9}, {%0,%1,%2,%3};\n"
        : "+f"(c[0]), "+f"(c[1]), "+f"(c[2]), "+f"(c[3])
        : "r"(a[0]), "r"(a[1]), "r"(a[2]), "r"(a[3]), "r"(b[0]), "r"(b[1]));
}
__device__ __forceinline__ void store_split2(__half* ph, __half* pl, float v0, float v1) {
    __half h0 = __float2half(v0);
    __half h1 = __float2half(v1);
    __half l0 = __float2half(v0 - __half2float(h0));
    __half l1 = __float2half(v1 - __half2float(h1));
    *reinterpret_cast<__half2*>(ph) = __halves2half2(h0, h1);
    *reinterpret_cast<__half2*>(pl) = __halves2half2(l0, l1);
}
__device__ __forceinline__ uint32_t pack_h2(float a, float b) {
    __half2 h = __floats2half2_rn(a, b);
    return *reinterpret_cast<uint32_t*>(&h);
}

// ------------------------------ prep kernels -------------------------------
__global__ void to_half_kernel(const float* __restrict__ src,
                               __half* __restrict__ dst, int n) {
    int i = blockIdx.x * blockDim.x + threadIdx.x;
    if (i < n) dst[i] = __float2half(src[i]);
}

__global__ void split_w1_kernel(const float* __restrict__ wq,
                                const float* __restrict__ wkv) {
    int i = blockIdx.x * blockDim.x + threadIdx.x;
    if (i >= KD * NC1) return;
    int k = i / NC1, n = i - k * NC1;
    float v = (n < KD) ? wq[k * KD + n] : wkv[k * 1024 + (n - KD)];
    __half h = __float2half(v);
    g_w1_h[i] = h;
    g_w1_l[i] = __float2half(v - __half2float(h));
}

__global__ void split_w3_kernel(const float* __restrict__ wproj) {
    int i = blockIdx.x * blockDim.x + threadIdx.x;
    if (i >= KD * KD) return;
    float v = wproj[i];
    __half h = __float2half(v);
    g_w3_h[i] = h;
    g_w3_l[i] = __float2half(v - __half2float(h));
}

// -------- 2-pass split-fp16 GEMM, 128x128x32 tiles, 3-stage pipeline -------
// C = A_fp16 * (Bh + Bl).  MODE 1: QKV epilogue (bias+scale, split out).
// MODE 3: fp32 out with bias.
template<int NCOLS, int MODE>
__global__ __launch_bounds__(256, 2)
void gemm_kernel(const __half* __restrict__ A,
                 const __half* __restrict__ Bh, const __half* __restrict__ Bl,
                 const float* __restrict__ bias0, const float* __restrict__ bias1,
                 __half* __restrict__ outh, __half* __restrict__ outl,
                 float* __restrict__ outf)
{
    constexpr int SA = 40;
    constexpr int SB = 136;
    constexpr int NB = NCOLS / 128;
    constexpr int GROUP_M = 16;
    constexpr int STAGE = 128 * SA + 2 * 32 * SB;   // 13824 halfs / stage
    constexpr int KITER = KD / 32;                  // 16

    extern __shared__ char smem_raw[];
    __half* smem = (__half*)smem_raw;

    int bid = blockIdx.x;
    int gsz = GROUP_M * NB;
    int grp = bid / gsz;
    int rem = bid - grp * gsz;
    int bm  = grp * GROUP_M + (rem % GROUP_M);
    int bn  = rem / GROUP_M;

    int tid = threadIdx.x, lane = tid & 31, wid = tid >> 5;
    int wm = wid & 3, wn = wid >> 2;
    const int arow = tid >> 2, acol8 = (tid & 3) * 8;
    const int brow = tid >> 4, bcol8 = (tid & 15) * 8;

    auto load_stage = [&](__half* sb, int k0) {
        __half* dA  = sb;
        __half* dBh = sb + 128 * SA;
        __half* dBl = dBh + 32 * SB;
        size_t ga = (size_t)(bm * 128 + arow) * KD + k0 + acol8;
        cp16(dA + arow * SA + acol8,        A + ga);
        cp16(dA + (arow + 64) * SA + acol8, A + ga + (size_t)64 * KD);
        size_t gb = (size_t)(k0 + brow) * NCOLS + bn * 128 + bcol8;
        cp16(dBh + brow * SB + bcol8,        Bh + gb);
        cp16(dBh + (brow + 16) * SB + bcol8, Bh + gb + (size_t)16 * NCOLS);
        cp16(dBl + brow * SB + bcol8,        Bl + gb);
        cp16(dBl + (brow + 16) * SB + bcol8, Bl + gb + (size_t)16 * NCOLS);
    };

    float acc[2][8][4];
    #pragma unroll
    for (int a = 0; a < 2; a++)
        #pragma unroll
        for (int b = 0; b < 8; b++)
            #pragma unroll
            for (int c = 0; c < 4; c++) acc[a][b][c] = 0.f;

    __half* bc  = smem;
    __half* bnx = smem + STAGE;
    __half* blw = smem + 2 * STAGE;

    load_stage(bc, 0);
    cp_commit();
    load_stage(bnx, 32);
    cp_commit();

    #pragma unroll 1
    for (int kt = 0; kt < KITER; kt++) {
        cp_wait<1>();
        __syncthreads();
        if (kt + 2 < KITER) load_stage(blw, (kt + 2) * 32);
        cp_commit();

        const __half* cA  = bc;
        const __half* cBh = bc + 128 * SA;
        const __half* cBl = cBh + 32 * SB;

        #pragma unroll
        for (int kk = 0; kk < 2; kk++) {
            uint32_t a0[4], a1[4];
            int ar = wm * 32 + (lane & 15);
            int ac = kk * 16 + (lane >> 4) * 8;
            ldsm4(a0, cA + ar * SA + ac);
            ldsm4(a1, cA + (ar + 16) * SA + ac);
            int br = kk * 16 + (lane & 15);
            #pragma unroll
            for (int nj2 = 0; nj2 < 4; nj2++) {
                int bcc = wn * 64 + nj2 * 16 + (lane >> 4) * 8;
                uint32_t bh[4], bl[4];
                ldsm4t(bh, cBh + br * SB + bcc);
                ldsm4t(bl, cBl + br * SB + bcc);
                #pragma unroll
                for (int t = 0; t < 2; t++) {
                    int nj = nj2 * 2 + t;
                    mma_f16(acc[0][nj], a0, bh + 2 * t);
                    mma_f16(acc[1][nj], a1, bh + 2 * t);
                    mma_f16(acc[0][nj], a0, bl + 2 * t);
                    mma_f16(acc[1][nj], a1, bl + 2 * t);
                }
            }
        }
        __half* tmp = bc;
        bc = bnx; bnx = blw; blw = tmp;
    }

    int row0 = bm * 128 + wm * 32 + (lane >> 2);
    int col0 = bn * 128 + wn * 64 + (lane & 3) * 2;
    #pragma unroll
    for (int mi = 0; mi < 2; mi++) {
        int ra = row0 + mi * 16;
        #pragma unroll
        for (int nj = 0; nj < 8; nj++) {
            int col = col0 + nj * 8;
            if (MODE == 1) {
                float b0, b1; float sc0, sc1;
                if (col < 512) { b0 = bias0[col]; b1 = bias0[col + 1]; sc0 = SCALE_Q; sc1 = SCALE_Q; }
                else { b0 = bias1[col - 512]; b1 = bias1[col - 511]; sc0 = 1.f; sc1 = 1.f; }
                size_t g0 = (size_t)ra * NCOLS + col;
                store_split2(outh + g0, outl + g0,
                             (acc[mi][nj][0] + b0) * sc0, (acc[mi][nj][1] + b1) * sc1);
                size_t g1 = (size_t)(ra + 8) * NCOLS + col;
                store_split2(outh + g1, outl + g1,
                             (acc[mi][nj][2] + b0) * sc0, (acc[mi][nj][3] + b1) * sc1);
            } else {
                float b0 = bias0[col], b1 = bias0[col + 1];
                float2 v01 = make_float2(acc[mi][nj][0] + b0, acc[mi][nj][1] + b1);
                float2 v23 = make_float2(acc[mi][nj][2] + b0, acc[mi][nj][3] + b1);
                *(float2*)&outf[(size_t)ra * NCOLS + col]       = v01;
                *(float2*)&outf[(size_t)(ra + 8) * NCOLS + col] = v23;
            }
        }
    }
}

// -------------- tensor-core attention (2-pass split-fp16 MMA) --------------
// 1 CTA (4 warps) per (window, head).  S = Qh*(Kh+Kl); exact fp32 softmax;
// attn stored from fragments; O = P_fp16*(Vh+Vl), O stored plain fp16.
__global__ __launch_bounds__(128)
void attn_mma_kernel(const __half* __restrict__ qkvh,
                     const __half* __restrict__ qkvl,
                     const float* __restrict__ table,
                     const int* __restrict__ relidx,
                     float* __restrict__ attn_out,
                     __half* __restrict__ oh)
{
    constexpr int SQ = 40;
    extern __shared__ char smraw[];
    __half* sT = (__half*)smraw;                       // 5 x [64*SQ] : Qh Kh Kl Vh Vl
    float*   sTab = (float*)(smraw + 5 * 64 * SQ * 2);
    uint8_t* sIdx = (uint8_t*)(sTab + 232);

    const int w = blockIdx.x >> 4, h = blockIdx.x & 15;
    const int tid = threadIdx.x, lane = tid & 31, wr = tid >> 5;
    const size_t rowbase = (size_t)(w * 64) * NC1;

    // tiles: 0:Qh(hi,+0) 1:Kh(hi,+512) 2:Kl(lo,+512) 3:Vh(hi,+1024) 4:Vl(lo,+1024)
    #pragma unroll
    for (int it = 0; it < 10; it++) {
        int e = tid + it * 128;
        int a = e >> 8;
        int rem = e & 255;
        int i = rem >> 2, c = (rem & 3) * 8;
        const __half* src = (a == 2 || a == 4) ? qkvl : qkvh;
        int off = (a == 0) ? 0 : ((a <= 2) ? 512 : 1024);
        size_t g = rowbase + (size_t)i * NC1 + h * 32 + off + c;
        cp16(sT + a * (64 * SQ) + i * SQ + c, src + g);
    }
    cp_commit();
    for (int t = tid; t < 4096; t += 128) sIdx[t] = (uint8_t)relidx[t];
    for (int t = tid; t < 225;  t += 128) sTab[t] = table[t * NHEADS + h];
    cp_wait<0>();
    __syncthreads();

    const __half* sQh = sT;
    const __half* sKh = sT + 1 * (64 * SQ);
    const __half* sKl = sT + 2 * (64 * SQ);
    const __half* sVh = sT + 3 * (64 * SQ);
    const __half* sVl = sT + 4 * (64 * SQ);

    const int r0 = wr * 16;

    uint32_t qa[2][4];
    #pragma unroll
    for (int kc = 0; kc < 2; kc++) {
        int ad = (r0 + (lane & 15)) * SQ + kc * 16 + (lane >> 4) * 8;
        ldsm4(qa[kc], sQh + ad);
    }
    float acc[8][4];
    #pragma unroll
    for (int j = 0; j < 8; j++)
        #pragma unroll
        for (int c = 0; c < 4; c++) acc[j][c] = 0.f;

    #pragma unroll
    for (int kc = 0; kc < 2; kc++) {
        #pragma unroll
        for (int jj = 0; jj < 4; jj++) {
            int row = jj * 16 + (lane & 7) + ((lane >> 4) & 1) * 8;
            int col = kc * 16 + ((lane >> 3) & 1) * 8;
            uint32_t kh[4], kl[4];
            ldsm4(kh, sKh + row * SQ + col);
            ldsm4(kl, sKl + row * SQ + col);
            mma_f16(acc[2 * jj],     qa[kc], kh);
            mma_f16(acc[2 * jj + 1], qa[kc], kh + 2);
            mma_f16(acc[2 * jj],     qa[kc], kl);
            mma_f16(acc[2 * jj + 1], qa[kc], kl + 2);
        }
    }

    const int rA = r0 + (lane >> 2), rB = rA + 8;
    const int cb = (lane & 3) * 2;
    float mA = -1e30f, mB = -1e30f;
    #pragma unroll
    for (int j = 0; j < 8; j++) {
        int c0 = j * 8 + cb;
        acc[j][0] += sTab[sIdx[rA * 64 + c0]];
        acc[j][1] += sTab[sIdx[rA * 64 + c0 + 1]];
        acc[j][2] += sTab[sIdx[rB * 64 + c0]];
        acc[j][3] += sTab[sIdx[rB * 64 + c0 + 1]];
        mA = fmaxf(mA, fmaxf(acc[j][0], acc[j][1]));
        mB = fmaxf(mB, fmaxf(acc[j][2], acc[j][3]));
    }
    mA = fmaxf(mA, __shfl_xor_sync(0xffffffffu, mA, 1));
    mA = fmaxf(mA, __shfl_xor_sync(0xffffffffu, mA, 2));
    mB = fmaxf(mB, __shfl_xor_sync(0xffffffffu, mB, 1));
    mB = fmaxf(mB, __shfl_xor_sync(0xffffffffu, mB, 2));
    float sA = 0.f, sB = 0.f;
    #pragma unroll
    for (int j = 0; j < 8; j++) {
        acc[j][0] = __expf(acc[j][0] - mA);
        acc[j][1] = __expf(acc[j][1] - mA);
        acc[j][2] = __expf(acc[j][2] - mB);
        acc[j][3] = __expf(acc[j][3] - mB);
        sA += acc[j][0] + acc[j][1];
        sB += acc[j][2] + acc[j][3];
    }
    sA += __shfl_xor_sync(0xffffffffu, sA, 1);
    sA += __shfl_xor_sync(0xffffffffu, sA, 2);
    sB += __shfl_xor_sync(0xffffffffu, sB, 1);
    sB += __shfl_xor_sync(0xffffffffu, sB, 2);
    const float invA = 1.f / sA, invB = 1.f / sB;

    uint32_t pa[4][4];
    const size_t abase = (size_t)blockIdx.x * 64;
    #pragma unroll
    for (int j = 0; j < 8; j++) {
        float p0 = acc[j][0] * invA, p1 = acc[j][1] * invA;
        float p2 = acc[j][2] * invB, p3 = acc[j][3] * invB;
        *(float2*)&attn_out[(abase + rA) * 64 + j * 8 + cb] = make_float2(p0, p1);
        *(float2*)&attn_out[(abase + rB) * 64 + j * 8 + cb] = make_float2(p2, p3);
        int t = j >> 1, s = (j & 1) * 2;
        pa[t][s + 0] = pack_h2(p0, p1);
        pa[t][s + 1] = pack_h2(p2, p3);
    }

    float o[4][4];
    #pragma unroll
    for (int nj = 0; nj < 4; nj++)
        #pragma unroll
        for (int c = 0; c < 4; c++) o[nj][c] = 0.f;
    #pragma unroll
    for (int kc = 0; kc < 4; kc++) {
        #pragma unroll
        for (int vb = 0; vb < 2; vb++) {
            int ad = (kc * 16 + (lane & 15)) * SQ + vb * 16 + (lane >> 4) * 8;
            uint32_t vh[4], vl[4];
            ldsm4t(vh, sVh + ad);
            ldsm4t(vl, sVl + ad);
            mma_f16(o[vb * 2],     pa[kc], vh);
            mma_f16(o[vb * 2 + 1], pa[kc], vh + 2);
            mma_f16(o[vb * 2],     pa[kc], vl);
            mma_f16(o[vb * 2 + 1], pa[kc], vl + 2);
        }
    }

    #pragma unroll
    for (int nj = 0; nj < 4; nj++) {
        int col = h * 32 + nj * 8 + cb;
        size_t gA = (size_t)(w * 64 + rA) * KD + col;
        size_t gB = (size_t)(w * 64 + rB) * KD + col;
        *(__half2*)&oh[gA] = __floats2half2_rn(o[nj][0], o[nj][1]);
        *(__half2*)&oh[gB] = __floats2half2_rn(o[nj][2], o[nj][3]);
    }
}

// ------------------------------- launcher ----------------------------------
extern "C" void kernel_launch(void* const* d_in, const int* in_sizes, int n_in,
                              void* d_out, int out_size) {
    const float* q      = (const float*)d_in[0];
    const float* wq     = (const float*)d_in[1];
    const float* bq     = (const float*)d_in[2];
    const float* wkv    = (const float*)d_in[3];
    const float* bkv    = (const float*)d_in[4];
    const float* wproj  = (const float*)d_in[5];
    const float* bproj  = (const float*)d_in[6];
    const float* table  = (const float*)d_in[7];
    const int*   relidx = (const int*)d_in[8];

    float* out_x    = (float*)d_out;
    float* out_attn = out_x + (size_t)TOKENS * KD;

    __half *q_h, *w1_h, *w1_l, *w3_h, *w3_l, *qkv_h, *qkv_l, *o_h;
    cudaGetSymbolAddress((void**)&q_h,   g_q_h);
    cudaGetSymbolAddress((void**)&w1_h,  g_w1_h);
    cudaGetSymbolAddress((void**)&w1_l,  g_w1_l);
    cudaGetSymbolAddress((void**)&w3_h,  g_w3_h);
    cudaGetSymbolAddress((void**)&w3_l,  g_w3_l);
    cudaGetSymbolAddress((void**)&qkv_h, g_qkv_h);
    cudaGetSymbolAddress((void**)&qkv_l, g_qkv_l);
    cudaGetSymbolAddress((void**)&o_h,   g_o_h);

    const int smem_gemm = 3 * (128 * 40 + 2 * 32 * 136) * 2;     // 82,944
    const int smem_attn = 5 * 64 * 40 * 2 + 232 * 4 + 4096;      // 30,624
    cudaFuncSetAttribute(gemm_kernel<NC1, 1>, cudaFuncAttributeMaxDynamicSharedMemorySize, smem_gemm);
    cudaFuncSetAttribute(gemm_kernel<KD, 3>,  cudaFuncAttributeMaxDynamicSharedMemorySize, smem_gemm);
    cudaFuncSetAttribute(attn_mma_kernel, cudaFuncAttributeMaxDynamicSharedMemorySize, smem_attn);

    to_half_kernel<<<(TOKENS * KD) / 256, 256>>>(q, q_h, TOKENS * KD);
    split_w1_kernel<<<(KD * NC1) / 256, 256>>>(wq, wkv);
    split_w3_kernel<<<(KD * KD) / 256, 256>>>(wproj);

    gemm_kernel<NC1, 1><<<(TOKENS / 128) * (NC1 / 128), 256, smem_gemm>>>(
        q_h, w1_h, w1_l, bq, bkv, qkv_h, qkv_l, nullptr);

    attn_mma_kernel<<<1024 * NHEADS, 128, smem_attn>>>(
        qkv_h, qkv_l, table, relidx, out_attn, o_h);

    gemm_kernel<KD, 3><<<(TOKENS / 128) * (KD / 128), 256, smem_gemm>>>(
        o_h, w3_h, w3_l, bproj, nullptr, nullptr, nullptr, out_x);
}

// round 7
// speedup vs baseline: 2.3558x; 1.3435x over previous
#include <cuda_runtime.h>
#include <cuda_fp16.h>
#include <stdint.h>

#define TOKENS   65536
#define KD       512
#define NC1      1536
#define NHEADS   16
#define SCALE_Q  0.17677669529663688f

// ------------------------- device scratch (static) -------------------------
__device__ __half g_q_h  [TOKENS * KD];
__device__ __half g_w1_h [KD * NC1];
__device__ __half g_w3_h [KD * KD];
__device__ __half g_qkv_h[(size_t)TOKENS * NC1];
__device__ __half g_qkv_l[(size_t)TOKENS * NC1];
__device__ __half g_o_h  [TOKENS * KD];

// ------------------------------ PTX helpers --------------------------------
__device__ __forceinline__ uint32_t smem_u32(const void* p) {
    return (uint32_t)__cvta_generic_to_shared(p);
}
__device__ __forceinline__ void cp16(void* s, const void* g) {
    asm volatile("cp.async.cg.shared.global [%0], [%1], 16;\n"
                 :: "r"(smem_u32(s)), "l"(g));
}
__device__ __forceinline__ void cp_commit() { asm volatile("cp.async.commit_group;\n"); }
template<int N> __device__ __forceinline__ void cp_wait() {
    asm volatile("cp.async.wait_group %0;\n" :: "n"(N));
}
__device__ __forceinline__ void ldsm4(uint32_t r[4], const void* p) {
    asm volatile("ldmatrix.sync.aligned.m8n8.x4.shared.b16 {%0,%1,%2,%3}, [%4];\n"
        : "=r"(r[0]), "=r"(r[1]), "=r"(r[2]), "=r"(r[3]) : "r"(smem_u32(p)));
}
__device__ __forceinline__ void ldsm4t(uint32_t r[4], const void* p) {
    asm volatile("ldmatrix.sync.aligned.m8n8.x4.trans.shared.b16 {%0,%1,%2,%3}, [%4];\n"
        : "=r"(r[0]), "=r"(r[1]), "=r"(r[2]), "=r"(r[3]) : "r"(smem_u32(p)));
}
__device__ __forceinline__ void mma_f16(float c[4], const uint32_t a[4], const uint32_t b[2]) {
    asm volatile(
        "mma.sync.aligned.m16n8k16.row.col.f32.f16.f16.f32 "
        "{%0,%1,%2,%3}, {%4,%5,%6,%7}, {%8,%9}, {%0,%1,%2,%3};\n"
        : "+f"(c[0]), "+f"(c[1]), "+f"(c[2]), "+f"(c[3])
        : "r"(a[0]), "r"(a[1]), "r"(a[2]), "r"(a[3]), "r"(b[0]), "r"(b[1]));
}
__device__ __forceinline__ void store_split2(__half* ph, __half* pl, float v0, float v1) {
    __half h0 = __float2half(v0);
    __half h1 = __float2half(v1);
    __half l0 = __float2half(v0 - __half2float(h0));
    __half l1 = __float2half(v1 - __half2float(h1));
    *reinterpret_cast<__half2*>(ph) = __halves2half2(h0, h1);
    *reinterpret_cast<__half2*>(pl) = __halves2half2(l0, l1);
}
__device__ __forceinline__ uint32_t pack_h2(float a, float b) {
    __half2 h = __floats2half2_rn(a, b);
    return *reinterpret_cast<uint32_t*>(&h);
}

// ------------------------------ prep kernels -------------------------------
__global__ void to_half_kernel(const float* __restrict__ src,
                               __half* __restrict__ dst, int n) {
    int i = blockIdx.x * blockDim.x + threadIdx.x;
    if (i < n) dst[i] = __float2half(src[i]);
}

__global__ void w1_half_kernel(const float* __restrict__ wq,
                               const float* __restrict__ wkv) {
    int i = blockIdx.x * blockDim.x + threadIdx.x;
    if (i >= KD * NC1) return;
    int k = i / NC1, n = i - k * NC1;
    float v = (n < KD) ? wq[k * KD + n] : wkv[k * 1024 + (n - KD)];
    g_w1_h[i] = __float2half(v);
}

// ------------ single-pass fp16 GEMM, 128x128x32 tiles, 3-stage -------------
// C = A_fp16 * B_fp16 (fp32 accum). MODE 1: QKV epilogue (bias+scale,
// hi/lo split out for attention). MODE 3: fp32 out with bias.
template<int NCOLS, int MODE>
__global__ __launch_bounds__(256, 2)
void gemm_kernel(const __half* __restrict__ A, const __half* __restrict__ B,
                 const float* __restrict__ bias0, const float* __restrict__ bias1,
                 __half* __restrict__ outh, __half* __restrict__ outl,
                 float* __restrict__ outf)
{
    constexpr int SA = 40;
    constexpr int SB = 136;
    constexpr int NB = NCOLS / 128;
    constexpr int GROUP_M = 16;
    constexpr int STAGE = 128 * SA + 32 * SB;   // 9472 halfs / stage
    constexpr int KITER = KD / 32;              // 16

    extern __shared__ char smem_raw[];
    __half* smem = (__half*)smem_raw;

    int bid = blockIdx.x;
    int gsz = GROUP_M * NB;
    int grp = bid / gsz;
    int rem = bid - grp * gsz;
    int bm  = grp * GROUP_M + (rem % GROUP_M);
    int bn  = rem / GROUP_M;

    int tid = threadIdx.x, lane = tid & 31, wid = tid >> 5;
    int wm = wid & 3, wn = wid >> 2;
    const int arow = tid >> 2, acol8 = (tid & 3) * 8;
    const int brow = tid >> 4, bcol8 = (tid & 15) * 8;

    auto load_stage = [&](__half* sb, int k0) {
        __half* dA = sb;
        __half* dB = sb + 128 * SA;
        size_t ga = (size_t)(bm * 128 + arow) * KD + k0 + acol8;
        cp16(dA + arow * SA + acol8,        A + ga);
        cp16(dA + (arow + 64) * SA + acol8, A + ga + (size_t)64 * KD);
        size_t gb = (size_t)(k0 + brow) * NCOLS + bn * 128 + bcol8;
        cp16(dB + brow * SB + bcol8,        B + gb);
        cp16(dB + (brow + 16) * SB + bcol8, B + gb + (size_t)16 * NCOLS);
    };

    float acc[2][8][4];
    #pragma unroll
    for (int a = 0; a < 2; a++)
        #pragma unroll
        for (int b = 0; b < 8; b++)
            #pragma unroll
            for (int c = 0; c < 4; c++) acc[a][b][c] = 0.f;

    __half* bc  = smem;
    __half* bnx = smem + STAGE;
    __half* blw = smem + 2 * STAGE;

    load_stage(bc, 0);
    cp_commit();
    load_stage(bnx, 32);
    cp_commit();

    #pragma unroll 1
    for (int kt = 0; kt < KITER; kt++) {
        cp_wait<1>();
        __syncthreads();
        if (kt + 2 < KITER) load_stage(blw, (kt + 2) * 32);
        cp_commit();

        const __half* cA = bc;
        const __half* cB = bc + 128 * SA;

        #pragma unroll
        for (int kk = 0; kk < 2; kk++) {
            uint32_t a0[4], a1[4];
            int ar = wm * 32 + (lane & 15);
            int ac = kk * 16 + (lane >> 4) * 8;
            ldsm4(a0, cA + ar * SA + ac);
            ldsm4(a1, cA + (ar + 16) * SA + ac);
            int br = kk * 16 + (lane & 15);
            #pragma unroll
            for (int nj2 = 0; nj2 < 4; nj2++) {
                int bcc = wn * 64 + nj2 * 16 + (lane >> 4) * 8;
                uint32_t bh[4];
                ldsm4t(bh, cB + br * SB + bcc);
                #pragma unroll
                for (int t = 0; t < 2; t++) {
                    int nj = nj2 * 2 + t;
                    mma_f16(acc[0][nj], a0, bh + 2 * t);
                    mma_f16(acc[1][nj], a1, bh + 2 * t);
                }
            }
        }
        __half* tmp = bc;
        bc = bnx; bnx = blw; blw = tmp;
    }

    int row0 = bm * 128 + wm * 32 + (lane >> 2);
    int col0 = bn * 128 + wn * 64 + (lane & 3) * 2;
    #pragma unroll
    for (int mi = 0; mi < 2; mi++) {
        int ra = row0 + mi * 16;
        #pragma unroll
        for (int nj = 0; nj < 8; nj++) {
            int col = col0 + nj * 8;
            if (MODE == 1) {
                float b0, b1; float sc0, sc1;
                if (col < 512) { b0 = bias0[col]; b1 = bias0[col + 1]; sc0 = SCALE_Q; sc1 = SCALE_Q; }
                else { b0 = bias1[col - 512]; b1 = bias1[col - 511]; sc0 = 1.f; sc1 = 1.f; }
                size_t g0 = (size_t)ra * NCOLS + col;
                store_split2(outh + g0, outl + g0,
                             (acc[mi][nj][0] + b0) * sc0, (acc[mi][nj][1] + b1) * sc1);
                size_t g1 = (size_t)(ra + 8) * NCOLS + col;
                store_split2(outh + g1, outl + g1,
                             (acc[mi][nj][2] + b0) * sc0, (acc[mi][nj][3] + b1) * sc1);
            } else {
                float b0 = bias0[col], b1 = bias0[col + 1];
                float2 v01 = make_float2(acc[mi][nj][0] + b0, acc[mi][nj][1] + b1);
                float2 v23 = make_float2(acc[mi][nj][2] + b0, acc[mi][nj][3] + b1);
                *(float2*)&outf[(size_t)ra * NCOLS + col]       = v01;
                *(float2*)&outf[(size_t)(ra + 8) * NCOLS + col] = v23;
            }
        }
    }
}

// -------------- tensor-core attention (2-pass split-fp16 MMA) --------------
// Unchanged from R6: S = Qh*(Kh+Kl); exact fp32 softmax; attn from fragments;
// O = P_fp16*(Vh+Vl), stored plain fp16.
__global__ __launch_bounds__(128)
void attn_mma_kernel(const __half* __restrict__ qkvh,
                     const __half* __restrict__ qkvl,
                     const float* __restrict__ table,
                     const int* __restrict__ relidx,
                     float* __restrict__ attn_out,
                     __half* __restrict__ oh)
{
    constexpr int SQ = 40;
    extern __shared__ char smraw[];
    __half* sT = (__half*)smraw;                       // 5 x [64*SQ] : Qh Kh Kl Vh Vl
    float*   sTab = (float*)(smraw + 5 * 64 * SQ * 2);
    uint8_t* sIdx = (uint8_t*)(sTab + 232);

    const int w = blockIdx.x >> 4, h = blockIdx.x & 15;
    const int tid = threadIdx.x, lane = tid & 31, wr = tid >> 5;
    const size_t rowbase = (size_t)(w * 64) * NC1;

    #pragma unroll
    for (int it = 0; it < 10; it++) {
        int e = tid + it * 128;
        int a = e >> 8;
        int rem = e & 255;
        int i = rem >> 2, c = (rem & 3) * 8;
        const __half* src = (a == 2 || a == 4) ? qkvl : qkvh;
        int off = (a == 0) ? 0 : ((a <= 2) ? 512 : 1024);
        size_t g = rowbase + (size_t)i * NC1 + h * 32 + off + c;
        cp16(sT + a * (64 * SQ) + i * SQ + c, src + g);
    }
    cp_commit();
    for (int t = tid; t < 4096; t += 128) sIdx[t] = (uint8_t)relidx[t];
    for (int t = tid; t < 225;  t += 128) sTab[t] = table[t * NHEADS + h];
    cp_wait<0>();
    __syncthreads();

    const __half* sQh = sT;
    const __half* sKh = sT + 1 * (64 * SQ);
    const __half* sKl = sT + 2 * (64 * SQ);
    const __half* sVh = sT + 3 * (64 * SQ);
    const __half* sVl = sT + 4 * (64 * SQ);

    const int r0 = wr * 16;

    uint32_t qa[2][4];
    #pragma unroll
    for (int kc = 0; kc < 2; kc++) {
        int ad = (r0 + (lane & 15)) * SQ + kc * 16 + (lane >> 4) * 8;
        ldsm4(qa[kc], sQh + ad);
    }
    float acc[8][4];
    #pragma unroll
    for (int j = 0; j < 8; j++)
        #pragma unroll
        for (int c = 0; c < 4; c++) acc[j][c] = 0.f;

    #pragma unroll
    for (int kc = 0; kc < 2; kc++) {
        #pragma unroll
        for (int jj = 0; jj < 4; jj++) {
            int row = jj * 16 + (lane & 7) + ((lane >> 4) & 1) * 8;
            int col = kc * 16 + ((lane >> 3) & 1) * 8;
            uint32_t kh[4], kl[4];
            ldsm4(kh, sKh + row * SQ + col);
            ldsm4(kl, sKl + row * SQ + col);
            mma_f16(acc[2 * jj],     qa[kc], kh);
            mma_f16(acc[2 * jj + 1], qa[kc], kh + 2);
            mma_f16(acc[2 * jj],     qa[kc], kl);
            mma_f16(acc[2 * jj + 1], qa[kc], kl + 2);
        }
    }

    const int rA = r0 + (lane >> 2), rB = rA + 8;
    const int cb = (lane & 3) * 2;
    float mA = -1e30f, mB = -1e30f;
    #pragma unroll
    for (int j = 0; j < 8; j++) {
        int c0 = j * 8 + cb;
        acc[j][0] += sTab[sIdx[rA * 64 + c0]];
        acc[j][1] += sTab[sIdx[rA * 64 + c0 + 1]];
        acc[j][2] += sTab[sIdx[rB * 64 + c0]];
        acc[j][3] += sTab[sIdx[rB * 64 + c0 + 1]];
        mA = fmaxf(mA, fmaxf(acc[j][0], acc[j][1]));
        mB = fmaxf(mB, fmaxf(acc[j][2], acc[j][3]));
    }
    mA = fmaxf(mA, __shfl_xor_sync(0xffffffffu, mA, 1));
    mA = fmaxf(mA, __shfl_xor_sync(0xffffffffu, mA, 2));
    mB = fmaxf(mB, __shfl_xor_sync(0xffffffffu, mB, 1));
    mB = fmaxf(mB, __shfl_xor_sync(0xffffffffu, mB, 2));
    float sA = 0.f, sB = 0.f;
    #pragma unroll
    for (int j = 0; j < 8; j++) {
        acc[j][0] = __expf(acc[j][0] - mA);
        acc[j][1] = __expf(acc[j][1] - mA);
        acc[j][2] = __expf(acc[j][2] - mB);
        acc[j][3] = __expf(acc[j][3] - mB);
        sA += acc[j][0] + acc[j][1];
        sB += acc[j][2] + acc[j][3];
    }
    sA += __shfl_xor_sync(0xffffffffu, sA, 1);
    sA += __shfl_xor_sync(0xffffffffu, sA, 2);
    sB += __shfl_xor_sync(0xffffffffu, sB, 1);
    sB += __shfl_xor_sync(0xffffffffu, sB, 2);
    const float invA = 1.f / sA, invB = 1.f / sB;

    uint32_t pa[4][4];
    const size_t abase = (size_t)blockIdx.x * 64;
    #pragma unroll
    for (int j = 0; j < 8; j++) {
        float p0 = acc[j][0] * invA, p1 = acc[j][1] * invA;
        float p2 = acc[j][2] * invB, p3 = acc[j][3] * invB;
        *(float2*)&attn_out[(abase + rA) * 64 + j * 8 + cb] = make_float2(p0, p1);
        *(float2*)&attn_out[(abase + rB) * 64 + j * 8 + cb] = make_float2(p2, p3);
        int t = j >> 1, s = (j & 1) * 2;
        pa[t][s + 0] = pack_h2(p0, p1);
        pa[t][s + 1] = pack_h2(p2, p3);
    }

    float o[4][4];
    #pragma unroll
    for (int nj = 0; nj < 4; nj++)
        #pragma unroll
        for (int c = 0; c < 4; c++) o[nj][c] = 0.f;
    #pragma unroll
    for (int kc = 0; kc < 4; kc++) {
        #pragma unroll
        for (int vb = 0; vb < 2; vb++) {
            int ad = (kc * 16 + (lane & 15)) * SQ + vb * 16 + (lane >> 4) * 8;
            uint32_t vh[4], vl[4];
            ldsm4t(vh, sVh + ad);
            ldsm4t(vl, sVl + ad);
            mma_f16(o[vb * 2],     pa[kc], vh);
            mma_f16(o[vb * 2 + 1], pa[kc], vh + 2);
            mma_f16(o[vb * 2],     pa[kc], vl);
            mma_f16(o[vb * 2 + 1], pa[kc], vl + 2);
        }
    }

    #pragma unroll
    for (int nj = 0; nj < 4; nj++) {
        int col = h * 32 + nj * 8 + cb;
        size_t gA = (size_t)(w * 64 + rA) * KD + col;
        size_t gB = (size_t)(w * 64 + rB) * KD + col;
        *(__half2*)&oh[gA] = __floats2half2_rn(o[nj][0], o[nj][1]);
        *(__half2*)&oh[gB] = __floats2half2_rn(o[nj][2], o[nj][3]);
    }
}

// ------------------------------- launcher ----------------------------------
extern "C" void kernel_launch(void* const* d_in, const int* in_sizes, int n_in,
                              void* d_out, int out_size) {
    const float* q      = (const float*)d_in[0];
    const float* wq     = (const float*)d_in[1];
    const float* bq     = (const float*)d_in[2];
    const float* wkv    = (const float*)d_in[3];
    const float* bkv    = (const float*)d_in[4];
    const float* wproj  = (const float*)d_in[5];
    const float* bproj  = (const float*)d_in[6];
    const float* table  = (const float*)d_in[7];
    const int*   relidx = (const int*)d_in[8];

    float* out_x    = (float*)d_out;
    float* out_attn = out_x + (size_t)TOKENS * KD;

    __half *q_h, *w1_h, *w3_h, *qkv_h, *qkv_l, *o_h;
    cudaGetSymbolAddress((void**)&q_h,   g_q_h);
    cudaGetSymbolAddress((void**)&w1_h,  g_w1_h);
    cudaGetSymbolAddress((void**)&w3_h,  g_w3_h);
    cudaGetSymbolAddress((void**)&qkv_h, g_qkv_h);
    cudaGetSymbolAddress((void**)&qkv_l, g_qkv_l);
    cudaGetSymbolAddress((void**)&o_h,   g_o_h);

    const int smem_gemm = 3 * (128 * 40 + 32 * 136) * 2;         // 56,832
    const int smem_attn = 5 * 64 * 40 * 2 + 232 * 4 + 4096;      // 30,624
    cudaFuncSetAttribute(gemm_kernel<NC1, 1>, cudaFuncAttributeMaxDynamicSharedMemorySize, smem_gemm);
    cudaFuncSetAttribute(gemm_kernel<KD, 3>,  cudaFuncAttributeMaxDynamicSharedMemorySize, smem_gemm);
    cudaFuncSetAttribute(attn_mma_kernel, cudaFuncAttributeMaxDynamicSharedMemorySize, smem_attn);

    to_half_kernel<<<(TOKENS * KD) / 256, 256>>>(q, q_h, TOKENS * KD);
    w1_half_kernel<<<(KD * NC1) / 256, 256>>>(wq, wkv);
    to_half_kernel<<<(KD * KD) / 256, 256>>>(wproj, w3_h, KD * KD);

    gemm_kernel<NC1, 1><<<(TOKENS / 128) * (NC1 / 128), 256, smem_gemm>>>(
        q_h, w1_h, bq, bkv, qkv_h, qkv_l, nullptr);

    attn_mma_kernel<<<1024 * NHEADS, 128, smem_attn>>>(
        qkv_h, qkv_l, table, relidx, out_attn, o_h);

    gemm_kernel<KD, 3><<<(TOKENS / 128) * (KD / 128), 256, smem_gemm>>>(
        o_h, w3_h, bproj, nullptr, nullptr, nullptr, out_x);
}

// round 8
// speedup vs baseline: 2.5074x; 1.0644x over previous
#include <cuda_runtime.h>
#include <cuda_fp16.h>
#include <stdint.h>

#define TOKENS   65536
#define KD       512
#define NC1      1536
#define NHEADS   16
#define SCALE_Q  0.17677669529663688f

// ------------------------- device scratch (static) -------------------------
__device__ __half g_q_h  [TOKENS * KD];
__device__ __half g_w1_h [KD * NC1];
__device__ __half g_w3_h [KD * KD];
__device__ __half g_qkv_h[(size_t)TOKENS * NC1];
__device__ __half g_qkv_l[(size_t)TOKENS * NC1];
__device__ __half g_o_h  [TOKENS * KD];

// ------------------------------ PTX helpers --------------------------------
__device__ __forceinline__ uint32_t smem_u32(const void* p) {
    return (uint32_t)__cvta_generic_to_shared(p);
}
__device__ __forceinline__ void cp16(void* s, const void* g) {
    asm volatile("cp.async.cg.shared.global [%0], [%1], 16;\n"
                 :: "r"(smem_u32(s)), "l"(g));
}
__device__ __forceinline__ void cp_commit() { asm volatile("cp.async.commit_group;\n"); }
template<int N> __device__ __forceinline__ void cp_wait() {
    asm volatile("cp.async.wait_group %0;\n" :: "n"(N));
}
__device__ __forceinline__ void ldsm4(uint32_t r[4], const void* p) {
    asm volatile("ldmatrix.sync.aligned.m8n8.x4.shared.b16 {%0,%1,%2,%3}, [%4];\n"
        : "=r"(r[0]), "=r"(r[1]), "=r"(r[2]), "=r"(r[3]) : "r"(smem_u32(p)));
}
__device__ __forceinline__ void ldsm4t(uint32_t r[4], const void* p) {
    asm volatile("ldmatrix.sync.aligned.m8n8.x4.trans.shared.b16 {%0,%1,%2,%3}, [%4];\n"
        : "=r"(r[0]), "=r"(r[1]), "=r"(r[2]), "=r"(r[3]) : "r"(smem_u32(p)));
}
__device__ __forceinline__ void mma_f16(float c[4], const uint32_t a[4], const uint32_t b[2]) {
    asm volatile(
        "mma.sync.aligned.m16n8k16.row.col.f32.f16.f16.f32 "
        "{%0,%1,%2,%3}, {%4,%5,%6,%7}, {%8,%9}, {%0,%1,%2,%3};\n"
        : "+f"(c[0]), "+f"(c[1]), "+f"(c[2]), "+f"(c[3])
        : "r"(a[0]), "r"(a[1]), "r"(a[2]), "r"(a[3]), "r"(b[0]), "r"(b[1]));
}
__device__ __forceinline__ void store_split2(__half* ph, __half* pl, float v0, float v1) {
    __half h0 = __float2half(v0);
    __half h1 = __float2half(v1);
    __half l0 = __float2half(v0 - __half2float(h0));
    __half l1 = __float2half(v1 - __half2float(h1));
    *reinterpret_cast<__half2*>(ph) = __halves2half2(h0, h1);
    *reinterpret_cast<__half2*>(pl) = __halves2half2(l0, l1);
}
__device__ __forceinline__ uint32_t pack_h2(float a, float b) {
    __half2 h = __floats2half2_rn(a, b);
    return *reinterpret_cast<uint32_t*>(&h);
}

// ------------------------------ prep kernels -------------------------------
__global__ void to_half_kernel(const float* __restrict__ src,
                               __half* __restrict__ dst, int n) {
    int i = blockIdx.x * blockDim.x + threadIdx.x;
    if (i < n) dst[i] = __float2half(src[i]);
}

__global__ void w1_half_kernel(const float* __restrict__ wq,
                               const float* __restrict__ wkv) {
    int i = blockIdx.x * blockDim.x + threadIdx.x;
    if (i >= KD * NC1) return;
    int k = i / NC1, n = i - k * NC1;
    float v = (n < KD) ? wq[k * KD + n] : wkv[k * 1024 + (n - KD)];
    g_w1_h[i] = __float2half(v);
}

// -------- single-pass fp16 GEMM, 128x128x32 tiles, 4 warps @ m64n64 --------
// C = A_fp16 * B_fp16 (fp32 accum). MODE 1: QKV epilogue (bias+scale,
// hi/lo split out for attention). MODE 3: fp32 out with bias.
template<int NCOLS, int MODE>
__global__ __launch_bounds__(128, 2)
void gemm_kernel(const __half* __restrict__ A, const __half* __restrict__ B,
                 const float* __restrict__ bias0, const float* __restrict__ bias1,
                 __half* __restrict__ outh, __half* __restrict__ outl,
                 float* __restrict__ outf)
{
    constexpr int SA = 40;
    constexpr int SB = 136;
    constexpr int NB = NCOLS / 128;
    constexpr int GROUP_M = 16;
    constexpr int STAGE = 128 * SA + 32 * SB;   // 9472 halfs / stage
    constexpr int KITER = KD / 32;              // 16

    extern __shared__ char smem_raw[];
    __half* smem = (__half*)smem_raw;

    int bid = blockIdx.x;
    int gsz = GROUP_M * NB;
    int grp = bid / gsz;
    int rem = bid - grp * gsz;
    int bm  = grp * GROUP_M + (rem % GROUP_M);
    int bn  = rem / GROUP_M;

    int tid = threadIdx.x, lane = tid & 31, wid = tid >> 5;
    int wm = wid & 1, wn = wid >> 1;            // warp = 64x64 of the 128x128 tile
    const int arow = tid >> 2, acol8 = (tid & 3) * 8;   // A rows 0..31, x4 iters
    const int brow = tid >> 4, bcol8 = (tid & 15) * 8;  // B rows 0..7,  x4 iters

    auto load_stage = [&](__half* sb, int k0) {
        __half* dA = sb;
        __half* dB = sb + 128 * SA;
        #pragma unroll
        for (int i = 0; i < 4; i++) {
            size_t ga = (size_t)(bm * 128 + arow + 32 * i) * KD + k0 + acol8;
            cp16(dA + (arow + 32 * i) * SA + acol8, A + ga);
        }
        #pragma unroll
        for (int i = 0; i < 4; i++) {
            size_t gb = (size_t)(k0 + brow + 8 * i) * NCOLS + bn * 128 + bcol8;
            cp16(dB + (brow + 8 * i) * SB + bcol8, B + gb);
        }
    };

    float acc[4][8][4];
    #pragma unroll
    for (int a = 0; a < 4; a++)
        #pragma unroll
        for (int b = 0; b < 8; b++)
            #pragma unroll
            for (int c = 0; c < 4; c++) acc[a][b][c] = 0.f;

    __half* bc  = smem;
    __half* bnx = smem + STAGE;
    __half* blw = smem + 2 * STAGE;

    load_stage(bc, 0);
    cp_commit();
    load_stage(bnx, 32);
    cp_commit();

    #pragma unroll 1
    for (int kt = 0; kt < KITER; kt++) {
        cp_wait<1>();
        __syncthreads();
        if (kt + 2 < KITER) load_stage(blw, (kt + 2) * 32);
        cp_commit();

        const __half* cA = bc;
        const __half* cB = bc + 128 * SA;

        #pragma unroll
        for (int kk = 0; kk < 2; kk++) {
            uint32_t a[4][4];
            int ac = kk * 16 + (lane >> 4) * 8;
            #pragma unroll
            for (int mt = 0; mt < 4; mt++) {
                int ar = wm * 64 + mt * 16 + (lane & 15);
                ldsm4(a[mt], cA + ar * SA + ac);
            }
            int br = kk * 16 + (lane & 15);
            #pragma unroll
            for (int nj2 = 0; nj2 < 4; nj2++) {
                int bcc = wn * 64 + nj2 * 16 + (lane >> 4) * 8;
                uint32_t bh[4];
                ldsm4t(bh, cB + br * SB + bcc);
                #pragma unroll
                for (int t = 0; t < 2; t++) {
                    int nj = nj2 * 2 + t;
                    #pragma unroll
                    for (int mt = 0; mt < 4; mt++)
                        mma_f16(acc[mt][nj], a[mt], bh + 2 * t);
                }
            }
        }
        __half* tmp = bc;
        bc = bnx; bnx = blw; blw = tmp;
    }

    int row0 = bm * 128 + wm * 64 + (lane >> 2);
    int col0 = bn * 128 + wn * 64 + (lane & 3) * 2;
    #pragma unroll
    for (int mi = 0; mi < 4; mi++) {
        int ra = row0 + mi * 16;
        #pragma unroll
        for (int nj = 0; nj < 8; nj++) {
            int col = col0 + nj * 8;
            if (MODE == 1) {
                float b0, b1; float sc0, sc1;
                if (col < 512) { b0 = bias0[col]; b1 = bias0[col + 1]; sc0 = SCALE_Q; sc1 = SCALE_Q; }
                else { b0 = bias1[col - 512]; b1 = bias1[col - 511]; sc0 = 1.f; sc1 = 1.f; }
                size_t g0 = (size_t)ra * NCOLS + col;
                store_split2(outh + g0, outl + g0,
                             (acc[mi][nj][0] + b0) * sc0, (acc[mi][nj][1] + b1) * sc1);
                size_t g1 = (size_t)(ra + 8) * NCOLS + col;
                store_split2(outh + g1, outl + g1,
                             (acc[mi][nj][2] + b0) * sc0, (acc[mi][nj][3] + b1) * sc1);
            } else {
                float b0 = bias0[col], b1 = bias0[col + 1];
                float2 v01 = make_float2(acc[mi][nj][0] + b0, acc[mi][nj][1] + b1);
                float2 v23 = make_float2(acc[mi][nj][2] + b0, acc[mi][nj][3] + b1);
                *(float2*)&outf[(size_t)ra * NCOLS + col]       = v01;
                *(float2*)&outf[(size_t)(ra + 8) * NCOLS + col] = v23;
            }
        }
    }
}

// -------------- tensor-core attention (2-pass split-fp16 MMA) --------------
// Unchanged from R7: S = Qh*(Kh+Kl); exact fp32 softmax; attn from fragments;
// O = P_fp16*(Vh+Vl), stored plain fp16.
__global__ __launch_bounds__(128)
void attn_mma_kernel(const __half* __restrict__ qkvh,
                     const __half* __restrict__ qkvl,
                     const float* __restrict__ table,
                     const int* __restrict__ relidx,
                     float* __restrict__ attn_out,
                     __half* __restrict__ oh)
{
    constexpr int SQ = 40;
    extern __shared__ char smraw[];
    __half* sT = (__half*)smraw;                       // 5 x [64*SQ] : Qh Kh Kl Vh Vl
    float*   sTab = (float*)(smraw + 5 * 64 * SQ * 2);
    uint8_t* sIdx = (uint8_t*)(sTab + 232);

    const int w = blockIdx.x >> 4, h = blockIdx.x & 15;
    const int tid = threadIdx.x, lane = tid & 31, wr = tid >> 5;
    const size_t rowbase = (size_t)(w * 64) * NC1;

    #pragma unroll
    for (int it = 0; it < 10; it++) {
        int e = tid + it * 128;
        int a = e >> 8;
        int rem = e & 255;
        int i = rem >> 2, c = (rem & 3) * 8;
        const __half* src = (a == 2 || a == 4) ? qkvl : qkvh;
        int off = (a == 0) ? 0 : ((a <= 2) ? 512 : 1024);
        size_t g = rowbase + (size_t)i * NC1 + h * 32 + off + c;
        cp16(sT + a * (64 * SQ) + i * SQ + c, src + g);
    }
    cp_commit();
    for (int t = tid; t < 4096; t += 128) sIdx[t] = (uint8_t)relidx[t];
    for (int t = tid; t < 225;  t += 128) sTab[t] = table[t * NHEADS + h];
    cp_wait<0>();
    __syncthreads();

    const __half* sQh = sT;
    const __half* sKh = sT + 1 * (64 * SQ);
    const __half* sKl = sT + 2 * (64 * SQ);
    const __half* sVh = sT + 3 * (64 * SQ);
    const __half* sVl = sT + 4 * (64 * SQ);

    const int r0 = wr * 16;

    uint32_t qa[2][4];
    #pragma unroll
    for (int kc = 0; kc < 2; kc++) {
        int ad = (r0 + (lane & 15)) * SQ + kc * 16 + (lane >> 4) * 8;
        ldsm4(qa[kc], sQh + ad);
    }
    float acc[8][4];
    #pragma unroll
    for (int j = 0; j < 8; j++)
        #pragma unroll
        for (int c = 0; c < 4; c++) acc[j][c] = 0.f;

    #pragma unroll
    for (int kc = 0; kc < 2; kc++) {
        #pragma unroll
        for (int jj = 0; jj < 4; jj++) {
            int row = jj * 16 + (lane & 7) + ((lane >> 4) & 1) * 8;
            int col = kc * 16 + ((lane >> 3) & 1) * 8;
            uint32_t kh[4], kl[4];
            ldsm4(kh, sKh + row * SQ + col);
            ldsm4(kl, sKl + row * SQ + col);
            mma_f16(acc[2 * jj],     qa[kc], kh);
            mma_f16(acc[2 * jj + 1], qa[kc], kh + 2);
            mma_f16(acc[2 * jj],     qa[kc], kl);
            mma_f16(acc[2 * jj + 1], qa[kc], kl + 2);
        }
    }

    const int rA = r0 + (lane >> 2), rB = rA + 8;
    const int cb = (lane & 3) * 2;
    float mA = -1e30f, mB = -1e30f;
    #pragma unroll
    for (int j = 0; j < 8; j++) {
        int c0 = j * 8 + cb;
        acc[j][0] += sTab[sIdx[rA * 64 + c0]];
        acc[j][1] += sTab[sIdx[rA * 64 + c0 + 1]];
        acc[j][2] += sTab[sIdx[rB * 64 + c0]];
        acc[j][3] += sTab[sIdx[rB * 64 + c0 + 1]];
        mA = fmaxf(mA, fmaxf(acc[j][0], acc[j][1]));
        mB = fmaxf(mB, fmaxf(acc[j][2], acc[j][3]));
    }
    mA = fmaxf(mA, __shfl_xor_sync(0xffffffffu, mA, 1));
    mA = fmaxf(mA, __shfl_xor_sync(0xffffffffu, mA, 2));
    mB = fmaxf(mB, __shfl_xor_sync(0xffffffffu, mB, 1));
    mB = fmaxf(mB, __shfl_xor_sync(0xffffffffu, mB, 2));
    float sA = 0.f, sB = 0.f;
    #pragma unroll
    for (int j = 0; j < 8; j++) {
        acc[j][0] = __expf(acc[j][0] - mA);
        acc[j][1] = __expf(acc[j][1] - mA);
        acc[j][2] = __expf(acc[j][2] - mB);
        acc[j][3] = __expf(acc[j][3] - mB);
        sA += acc[j][0] + acc[j][1];
        sB += acc[j][2] + acc[j][3];
    }
    sA += __shfl_xor_sync(0xffffffffu, sA, 1);
    sA += __shfl_xor_sync(0xffffffffu, sA, 2);
    sB += __shfl_xor_sync(0xffffffffu, sB, 1);
    sB += __shfl_xor_sync(0xffffffffu, sB, 2);
    const float invA = 1.f / sA, invB = 1.f / sB;

    uint32_t pa[4][4];
    const size_t abase = (size_t)blockIdx.x * 64;
    #pragma unroll
    for (int j = 0; j < 8; j++) {
        float p0 = acc[j][0] * invA, p1 = acc[j][1] * invA;
        float p2 = acc[j][2] * invB, p3 = acc[j][3] * invB;
        *(float2*)&attn_out[(abase + rA) * 64 + j * 8 + cb] = make_float2(p0, p1);
        *(float2*)&attn_out[(abase + rB) * 64 + j * 8 + cb] = make_float2(p2, p3);
        int t = j >> 1, s = (j & 1) * 2;
        pa[t][s + 0] = pack_h2(p0, p1);
        pa[t][s + 1] = pack_h2(p2, p3);
    }

    float o[4][4];
    #pragma unroll
    for (int nj = 0; nj < 4; nj++)
        #pragma unroll
        for (int c = 0; c < 4; c++) o[nj][c] = 0.f;
    #pragma unroll
    for (int kc = 0; kc < 4; kc++) {
        #pragma unroll
        for (int vb = 0; vb < 2; vb++) {
            int ad = (kc * 16 + (lane & 15)) * SQ + vb * 16 + (lane >> 4) * 8;
            uint32_t vh[4], vl[4];
            ldsm4t(vh, sVh + ad);
            ldsm4t(vl, sVl + ad);
            mma_f16(o[vb * 2],     pa[kc], vh);
            mma_f16(o[vb * 2 + 1], pa[kc], vh + 2);
            mma_f16(o[vb * 2],     pa[kc], vl);
            mma_f16(o[vb * 2 + 1], pa[kc], vl + 2);
        }
    }

    #pragma unroll
    for (int nj = 0; nj < 4; nj++) {
        int col = h * 32 + nj * 8 + cb;
        size_t gA = (size_t)(w * 64 + rA) * KD + col;
        size_t gB = (size_t)(w * 64 + rB) * KD + col;
        *(__half2*)&oh[gA] = __floats2half2_rn(o[nj][0], o[nj][1]);
        *(__half2*)&oh[gB] = __floats2half2_rn(o[nj][2], o[nj][3]);
    }
}

// ------------------------------- launcher ----------------------------------
extern "C" void kernel_launch(void* const* d_in, const int* in_sizes, int n_in,
                              void* d_out, int out_size) {
    const float* q      = (const float*)d_in[0];
    const float* wq     = (const float*)d_in[1];
    const float* bq     = (const float*)d_in[2];
    const float* wkv    = (const float*)d_in[3];
    const float* bkv    = (const float*)d_in[4];
    const float* wproj  = (const float*)d_in[5];
    const float* bproj  = (const float*)d_in[6];
    const float* table  = (const float*)d_in[7];
    const int*   relidx = (const int*)d_in[8];

    float* out_x    = (float*)d_out;
    float* out_attn = out_x + (size_t)TOKENS * KD;

    __half *q_h, *w1_h, *w3_h, *qkv_h, *qkv_l, *o_h;
    cudaGetSymbolAddress((void**)&q_h,   g_q_h);
    cudaGetSymbolAddress((void**)&w1_h,  g_w1_h);
    cudaGetSymbolAddress((void**)&w3_h,  g_w3_h);
    cudaGetSymbolAddress((void**)&qkv_h, g_qkv_h);
    cudaGetSymbolAddress((void**)&qkv_l, g_qkv_l);
    cudaGetSymbolAddress((void**)&o_h,   g_o_h);

    const int smem_gemm = 3 * (128 * 40 + 32 * 136) * 2;         // 56,832
    const int smem_attn = 5 * 64 * 40 * 2 + 232 * 4 + 4096;      // 30,624
    cudaFuncSetAttribute(gemm_kernel<NC1, 1>, cudaFuncAttributeMaxDynamicSharedMemorySize, smem_gemm);
    cudaFuncSetAttribute(gemm_kernel<KD, 3>,  cudaFuncAttributeMaxDynamicSharedMemorySize, smem_gemm);
    cudaFuncSetAttribute(attn_mma_kernel, cudaFuncAttributeMaxDynamicSharedMemorySize, smem_attn);

    to_half_kernel<<<(TOKENS * KD) / 256, 256>>>(q, q_h, TOKENS * KD);
    w1_half_kernel<<<(KD * NC1) / 256, 256>>>(wq, wkv);
    to_half_kernel<<<(KD * KD) / 256, 256>>>(wproj, w3_h, KD * KD);

    gemm_kernel<NC1, 1><<<(TOKENS / 128) * (NC1 / 128), 128, smem_gemm>>>(
        q_h, w1_h, bq, bkv, qkv_h, qkv_l, nullptr);

    attn_mma_kernel<<<1024 * NHEADS, 128, smem_attn>>>(
        qkv_h, qkv_l, table, relidx, out_attn, o_h);

    gemm_kernel<KD, 3><<<(TOKENS / 128) * (KD / 128), 128, smem_gemm>>>(
        o_h, w3_h, bproj, nullptr, nullptr, nullptr, out_x);
}